// round 5
// baseline (speedup 1.0000x reference)
#include <cuda_runtime.h>
#include <math.h>

#define NB 4
#define NS 2048
#define ND 1024
#define NH 16
#define NDK 10
#define NDV 12
#define DP 12
#define NROW (NB*NS)          // 8192
#define NCOL (NH*DP)          // 192
#define KCELL 20              // 2 keys x 10 dims, pair-interleaved
#define VCELL 24              // 2 keys x 12 dims, pair-interleaved

// scratch (device globals: no allocation allowed)
__device__ float g_wpad[3*ND*NCOL];          // padded weights [z][k][h*12+j], Q pre-scaled
__device__ float g_qp[NB*NH*NS*DP];          // q*(log2e/sqrt10), 12-stride, cols 0..9 valid
__device__ float g_ki[NB*NH*(NS/2)*KCELL];   // K pairs: cell[2j+p] = k_{2t+p}[j]
__device__ float g_vi[NB*NH*(NS/2)*VCELL];   // V pairs: cell[2j+p] = v_{2t+p}[j]
__device__ float g_heads[NROW*NCOL];

typedef unsigned long long u64;

__device__ __forceinline__ u64 ffma2(u64 a, u64 b, u64 c) {
    u64 d; asm("fma.rn.f32x2 %0, %1, %2, %3;" : "=l"(d) : "l"(a), "l"(b), "l"(c)); return d;
}
__device__ __forceinline__ u64 fadd2(u64 a, u64 b) {
    u64 d; asm("add.rn.f32x2 %0, %1, %2;" : "=l"(d) : "l"(a), "l"(b)); return d;
}
__device__ __forceinline__ u64 pack2(float x, float y) {
    u64 r; asm("mov.b64 %0, {%1, %2};" : "=l"(r) : "f"(x), "f"(y)); return r;
}
__device__ __forceinline__ void unpack2(u64 v, float& x, float& y) {
    asm("mov.b64 {%0, %1}, %2;" : "=f"(x), "=f"(y) : "l"(v));
}
__device__ __forceinline__ float ex2f(float x) {
    float y; asm("ex2.approx.f32 %0, %1;" : "=f"(y) : "f"(x)); return y;
}

// ---------------------------------------------------------------------------
// Kernel 0: pad/transpose weights into [z][ND][192]; fold Q scale into WQ.
// ---------------------------------------------------------------------------
__global__ __launch_bounds__(256) void prep_kernel(
    const float* __restrict__ WQ, const float* __restrict__ WK, const float* __restrict__ WV)
{
    int idx = blockIdx.x * 256 + threadIdx.x;          // < 3*1024*192
    int z = idx / (ND * NCOL);
    int rem = idx - z * ND * NCOL;
    int k = rem / NCOL, c = rem - k * NCOL;
    int h = c / DP, j = c - h * DP;
    const float* W = (z == 0) ? WQ : ((z == 1) ? WK : WV);
    int dout = (z == 2) ? NDV : NDK;
    float v = (j < dout) ? W[(h * ND + k) * dout + j] : 0.0f;
    if (z == 0) v *= 1.4426950408889634f * rsqrtf((float)NDK);
    g_wpad[idx] = v;
}

// ---------------------------------------------------------------------------
// Kernel 1: QKV projection. grid (256,1,3), 128 threads, occ 5 -> 1.04 waves.
// CTA tile 32 rows x 192 cols, BK=16. Thread: 8 rows x 3 f32x2 cols.
// Warp = 4 rowgroups x 8 colgroups: A reads 1 wf (LDS.128 over 4 rg-cells),
// B reads 2 instr / 4 wf (cells padded to 8 floats). FFMA2-bound (1.5x margin).
// ---------------------------------------------------------------------------
__global__ __launch_bounds__(128, 5) void proj_kernel(
    const float* __restrict__ Q, const float* __restrict__ K, const float* __restrict__ V)
{
    __shared__ u64 As2[16 * 4 * 4 * 2];    // [kk][r2][rg][p], value duplicated
    __shared__ float Bs[16 * 32 * 8];      // [kk][cg][8] (6 valid + 2 pad)

    const int z = blockIdx.z;
    const float* X = (z == 0) ? Q : ((z == 1) ? K : V);
    const float* Wp = g_wpad + z * ND * NCOL;

    const int tid = threadIdx.x;
    const int rg  = (tid & 31) >> 3;               // 0..3
    const int cg  = (tid >> 5) * 8 + (tid & 7);    // 0..31
    const int row0 = blockIdx.x * 32;

    // A staging role: one float4 per thread
    const int arow = tid >> 2, aseg = tid & 3;
    const int ar2 = (arow & 7) >> 1, arg = arow >> 3, apar = arow & 1;
    const float* aptr = X + (size_t)(row0 + arow) * ND + aseg * 4;

    // B staging role: 6 float4 -> 12 STS.64 into padded cells (loop-invariant dsts)
    int bsrc[6], bdst0[6], bdst1[6];
    #pragma unroll
    for (int i = 0; i < 6; i++) {
        int f = tid + i * 128;                 // float4 index 0..767
        int kk = f / 48;
        int cf = (f - kk * 48) * 4;            // float col 0..188
        bsrc[i] = kk * NCOL + cf;
        int u = cf >> 1;                       // u64 col 0..95 (even cf)
        int cell = u / 3, s = u - cell * 3;
        bdst0[i] = kk * 128 + cell * 4 + s;
        int u2 = u + 1;
        int cell2 = u2 / 3, s2 = u2 - cell2 * 3;
        bdst1[i] = kk * 128 + cell2 * 4 + s2;
    }

    u64 acc[8][3];
    #pragma unroll
    for (int r = 0; r < 8; r++)
        #pragma unroll
        for (int c = 0; c < 3; c++) acc[r][c] = 0ull;

    for (int t = 0; t < ND / 16; t++) {
        const int k0 = t * 16;
        float4 a4 = *(const float4*)(aptr + k0);
        #pragma unroll
        for (int c = 0; c < 4; c++) {
            int kk = aseg * 4 + c;
            float v = (&a4.x)[c];
            As2[((kk * 4 + ar2) * 4 + arg) * 2 + apar] = pack2(v, v);
        }
        const float* wsrc = Wp + k0 * NCOL;
        u64* bu = (u64*)Bs;
        #pragma unroll
        for (int i = 0; i < 6; i++) {
            float4 b4 = *(const float4*)(wsrc + bsrc[i]);
            bu[bdst0[i]] = pack2(b4.x, b4.y);
            bu[bdst1[i]] = pack2(b4.z, b4.w);
        }
        __syncthreads();

        #pragma unroll
        for (int kk = 0; kk < 16; kk++) {
            const ulonglong2* ar = (const ulonglong2*)As2 + kk * 16 + rg;
            ulonglong2 a01 = ar[0], a23 = ar[4], a45 = ar[8], a67 = ar[12];
            const u64* bp = (const u64*)Bs + kk * 128 + cg * 4;
            ulonglong2 b01 = *(const ulonglong2*)bp;
            u64 b2 = bp[2];
            u64 a[8] = { a01.x, a01.y, a23.x, a23.y, a45.x, a45.y, a67.x, a67.y };
            #pragma unroll
            for (int r = 0; r < 8; r++) {
                acc[r][0] = ffma2(a[r], b01.x, acc[r][0]);
                acc[r][1] = ffma2(a[r], b01.y, acc[r][1]);
                acc[r][2] = ffma2(a[r], b2,    acc[r][2]);
            }
        }
        __syncthreads();
    }

    // epilogue: thread owns rows rg*8+r (r=0..7), f32 cols [cg*6, cg*6+6)
    float o[8][6];
    #pragma unroll
    for (int r = 0; r < 8; r++)
        #pragma unroll
        for (int c = 0; c < 3; c++) unpack2(acc[r][c], o[r][2 * c], o[r][2 * c + 1]);

    const int h = cg >> 1, j0 = (cg & 1) * 6;
    const int grow0 = row0 + rg * 8;
    const int b = grow0 >> 11, s0 = grow0 & 2047;
    const int bh = b * NH + h;

    if (z == 0) {            // Q (scale already folded): store dims < 10
        #pragma unroll
        for (int r = 0; r < 8; r++) {
            float* dst = g_qp + ((size_t)bh * NS + s0 + r) * DP + j0;
            #pragma unroll
            for (int jj = 0; jj < 6; jj += 2)
                if (j0 + jj < NDK)
                    *(float2*)(dst + jj) = make_float2(o[r][jj], o[r][jj + 1]);
        }
    } else if (z == 1) {     // K pair-interleaved cells (dims < 10)
        #pragma unroll
        for (int c = 0; c < 4; c++) {
            int s2 = (s0 >> 1) + c;
            u64* cell = (u64*)(g_ki + ((size_t)bh * (NS / 2) + s2) * KCELL);
            #pragma unroll
            for (int jj = 0; jj < 6; jj++) {
                int j = j0 + jj;
                if (j < NDK) cell[j] = pack2(o[2 * c][jj], o[2 * c + 1][jj]);
            }
        }
    } else {                 // V pair-interleaved cells (all 12 dims)
        #pragma unroll
        for (int c = 0; c < 4; c++) {
            int s2 = (s0 >> 1) + c;
            u64* cell = (u64*)(g_vi + ((size_t)bh * (NS / 2) + s2) * VCELL);
            #pragma unroll
            for (int jj = 0; jj < 6; jj++)
                cell[j0 + jj] = pack2(o[2 * c][jj], o[2 * c + 1][jj]);
        }
    }
}

// ---------------------------------------------------------------------------
// Kernel 2: attention. grid (2, 64), 512 threads; 2 q rows/thread.
// K (80KB) + V (96KB) pair-interleaved in smem; key-in-lane accumulators so
// exp2 outputs pair directly into the FFMA2 operand (no duplication MOVs).
// ---------------------------------------------------------------------------
__global__ __launch_bounds__(512, 1) void attn_kernel()
{
    extern __shared__ float smem[];
    float* ksf = smem;                       // [1024][20]
    float* vsf = smem + 1024 * KCELL;        // [1024][24]
    const int bh = blockIdx.y;
    const int tid = threadIdx.x;

    {
        const float4* ks = (const float4*)(g_ki + (size_t)bh * (NS / 2) * KCELL);
        float4* kd = (float4*)ksf;
        for (int i = tid; i < NS / 2 * KCELL / 4; i += 512) kd[i] = ks[i];
        const float4* vsrc = (const float4*)(g_vi + (size_t)bh * (NS / 2) * VCELL);
        float4* vd = (float4*)vsf;
        for (int i = tid; i < NS / 2 * VCELL / 4; i += 512) vd[i] = vsrc[i];
    }
    __syncthreads();

    const int rowA = blockIdx.x * 1024 + tid;
    const int rowB = rowA + 512;

    u64 qA[10], qB[10];
    {
        const float* qr = g_qp + ((size_t)bh * NS + rowA) * DP;
        float4 a = *(const float4*)qr, b4 = *(const float4*)(qr + 4);
        float2 c = *(const float2*)(qr + 8);
        float q[10] = { a.x, a.y, a.z, a.w, b4.x, b4.y, b4.z, b4.w, c.x, c.y };
        #pragma unroll
        for (int i = 0; i < 10; i++) qA[i] = pack2(q[i], q[i]);
    }
    {
        const float* qr = g_qp + ((size_t)bh * NS + rowB) * DP;
        float4 a = *(const float4*)qr, b4 = *(const float4*)(qr + 4);
        float2 c = *(const float2*)(qr + 8);
        float q[10] = { a.x, a.y, a.z, a.w, b4.x, b4.y, b4.z, b4.w, c.x, c.y };
        #pragma unroll
        for (int i = 0; i < 10; i++) qB[i] = pack2(q[i], q[i]);
    }

    u64 accA[12], accB[12];
    #pragma unroll
    for (int j = 0; j < 12; j++) { accA[j] = 0ull; accB[j] = 0ull; }
    u64 lA = 0ull, lB = 0ull;

    const ulonglong2* k2 = (const ulonglong2*)ksf;
    const ulonglong2* v2 = (const ulonglong2*)vsf;

    #pragma unroll 2
    for (int t2 = 0; t2 < NS / 2; t2++) {
        const ulonglong2* kc = k2 + (size_t)t2 * 5;
        ulonglong2 K0 = kc[0], K1 = kc[1], K2 = kc[2], K3 = kc[3], K4 = kc[4];

        // split dependency chains (5 deep each)
        u64 sA1 = 0ull, sA2 = 0ull, sB1 = 0ull, sB2 = 0ull;
        sA1 = ffma2(qA[0], K0.x, sA1);  sB1 = ffma2(qB[0], K0.x, sB1);
        sA2 = ffma2(qA[1], K0.y, sA2);  sB2 = ffma2(qB[1], K0.y, sB2);
        sA1 = ffma2(qA[2], K1.x, sA1);  sB1 = ffma2(qB[2], K1.x, sB1);
        sA2 = ffma2(qA[3], K1.y, sA2);  sB2 = ffma2(qB[3], K1.y, sB2);
        sA1 = ffma2(qA[4], K2.x, sA1);  sB1 = ffma2(qB[4], K2.x, sB1);
        sA2 = ffma2(qA[5], K2.y, sA2);  sB2 = ffma2(qB[5], K2.y, sB2);
        sA1 = ffma2(qA[6], K3.x, sA1);  sB1 = ffma2(qB[6], K3.x, sB1);
        sA2 = ffma2(qA[7], K3.y, sA2);  sB2 = ffma2(qB[7], K3.y, sB2);
        sA1 = ffma2(qA[8], K4.x, sA1);  sB1 = ffma2(qB[8], K4.x, sB1);
        sA2 = ffma2(qA[9], K4.y, sA2);  sB2 = ffma2(qB[9], K4.y, sB2);

        float s0A, s1A, s0B, s1B;
        unpack2(fadd2(sA1, sA2), s0A, s1A);
        unpack2(fadd2(sB1, sB2), s0B, s1B);
        u64 ppA = pack2(ex2f(s0A), ex2f(s1A));   // (p_even, p_odd)
        u64 ppB = pack2(ex2f(s0B), ex2f(s1B));
        lA = fadd2(lA, ppA);
        lB = fadd2(lB, ppB);

        const ulonglong2* vc = v2 + (size_t)t2 * 6;
        {
            ulonglong2 V0 = vc[0], V1 = vc[1], V2 = vc[2];
            accA[0] = ffma2(ppA, V0.x, accA[0]);  accB[0] = ffma2(ppB, V0.x, accB[0]);
            accA[1] = ffma2(ppA, V0.y, accA[1]);  accB[1] = ffma2(ppB, V0.y, accB[1]);
            accA[2] = ffma2(ppA, V1.x, accA[2]);  accB[2] = ffma2(ppB, V1.x, accB[2]);
            accA[3] = ffma2(ppA, V1.y, accA[3]);  accB[3] = ffma2(ppB, V1.y, accB[3]);
            accA[4] = ffma2(ppA, V2.x, accA[4]);  accB[4] = ffma2(ppB, V2.x, accB[4]);
            accA[5] = ffma2(ppA, V2.y, accA[5]);  accB[5] = ffma2(ppB, V2.y, accB[5]);
        }
        {
            ulonglong2 V3 = vc[3], V4 = vc[4], V5 = vc[5];
            accA[6]  = ffma2(ppA, V3.x, accA[6]);   accB[6]  = ffma2(ppB, V3.x, accB[6]);
            accA[7]  = ffma2(ppA, V3.y, accA[7]);   accB[7]  = ffma2(ppB, V3.y, accB[7]);
            accA[8]  = ffma2(ppA, V4.x, accA[8]);   accB[8]  = ffma2(ppB, V4.x, accB[8]);
            accA[9]  = ffma2(ppA, V4.y, accA[9]);   accB[9]  = ffma2(ppB, V4.y, accB[9]);
            accA[10] = ffma2(ppA, V5.x, accA[10]);  accB[10] = ffma2(ppB, V5.x, accB[10]);
            accA[11] = ffma2(ppA, V5.y, accA[11]);  accB[11] = ffma2(ppB, V5.y, accB[11]);
        }
    }

    const int b = bh >> 4, h = bh & 15;
    {
        float la0, la1; unpack2(lA, la0, la1);
        float inv = 1.0f / (la0 + la1);
        float o[12];
        #pragma unroll
        for (int j = 0; j < 12; j++) { float e, od; unpack2(accA[j], e, od); o[j] = (e + od) * inv; }
        float* dst = g_heads + (size_t)(b * NS + rowA) * NCOL + h * NDV;
        *(float4*)(dst + 0) = make_float4(o[0], o[1], o[2],  o[3]);
        *(float4*)(dst + 4) = make_float4(o[4], o[5], o[6],  o[7]);
        *(float4*)(dst + 8) = make_float4(o[8], o[9], o[10], o[11]);
    }
    {
        float lb0, lb1; unpack2(lB, lb0, lb1);
        float inv = 1.0f / (lb0 + lb1);
        float o[12];
        #pragma unroll
        for (int j = 0; j < 12; j++) { float e, od; unpack2(accB[j], e, od); o[j] = (e + od) * inv; }
        float* dst = g_heads + (size_t)(b * NS + rowB) * NCOL + h * NDV;
        *(float4*)(dst + 0) = make_float4(o[0], o[1], o[2],  o[3]);
        *(float4*)(dst + 4) = make_float4(o[4], o[5], o[6],  o[7]);
        *(float4*)(dst + 8) = make_float4(o[8], o[9], o[10], o[11]);
    }
}

// ---------------------------------------------------------------------------
// Kernel 3: output projection. [8192,192] x [192,1024]. grid (8,256),
// 128 threads, tile 32x128, occ 6. Warp 4rg x 8cg; B read = 1 LDS.128 = 1 wf.
// ---------------------------------------------------------------------------
__global__ __launch_bounds__(128, 6) void outproj_kernel(
    const float* __restrict__ WO, float* __restrict__ out)
{
    __shared__ u64 As2[16 * 4 * 4 * 2];    // [kk][r2][rg][p]
    __shared__ float Bs[16 * 128];

    const int tid = threadIdx.x;
    const int rg = (tid & 31) >> 3;
    const int cg = (tid >> 5) * 8 + (tid & 7);     // 0..31, 4 f32 each
    const int row0 = blockIdx.y * 32;
    const int col0 = blockIdx.x * 128;

    const int arow = tid >> 2, aseg = tid & 3;
    const int ar2 = (arow & 7) >> 1, arg = arow >> 3, apar = arow & 1;
    const float* aptr = g_heads + (size_t)(row0 + arow) * NCOL + aseg * 4;

    int bsrc[4], bdst[4];
    #pragma unroll
    for (int i = 0; i < 4; i++) {
        int f = tid + i * 128;                // float4 idx 0..511
        int kk = f >> 5, c = (f & 31) * 4;
        bsrc[i] = kk * ND + col0 + c;
        bdst[i] = kk * 128 + c;
    }

    u64 acc[8][2];
    #pragma unroll
    for (int r = 0; r < 8; r++) { acc[r][0] = 0ull; acc[r][1] = 0ull; }

    for (int t = 0; t < NCOL / 16; t++) {
        const int k0 = t * 16;
        float4 a4 = *(const float4*)(aptr + k0);
        #pragma unroll
        for (int c = 0; c < 4; c++) {
            int kk = aseg * 4 + c;
            float v = (&a4.x)[c];
            As2[((kk * 4 + ar2) * 4 + arg) * 2 + apar] = pack2(v, v);
        }
        #pragma unroll
        for (int i = 0; i < 4; i++)
            *(float4*)(Bs + bdst[i]) = *(const float4*)(WO + (size_t)k0 * ND + bsrc[i]);
        __syncthreads();

        #pragma unroll
        for (int kk = 0; kk < 16; kk++) {
            const ulonglong2* ar = (const ulonglong2*)As2 + kk * 16 + rg;
            ulonglong2 a01 = ar[0], a23 = ar[4], a45 = ar[8], a67 = ar[12];
            ulonglong2 bv = *(const ulonglong2*)(Bs + kk * 128 + cg * 4);
            u64 a[8] = { a01.x, a01.y, a23.x, a23.y, a45.x, a45.y, a67.x, a67.y };
            #pragma unroll
            for (int r = 0; r < 8; r++) {
                acc[r][0] = ffma2(a[r], bv.x, acc[r][0]);
                acc[r][1] = ffma2(a[r], bv.y, acc[r][1]);
            }
        }
        __syncthreads();
    }

    #pragma unroll
    for (int r = 0; r < 8; r++) {
        float o[4];
        unpack2(acc[r][0], o[0], o[1]);
        unpack2(acc[r][1], o[2], o[3]);
        float* dst = out + (size_t)(row0 + rg * 8 + r) * ND + col0 + cg * 4;
        *(float4*)dst = make_float4(o[0], o[1], o[2], o[3]);
    }
}

// ---------------------------------------------------------------------------
extern "C" void kernel_launch(void* const* d_in, const int* in_sizes, int n_in,
                              void* d_out, int out_size)
{
    const float* Q  = (const float*)d_in[0];
    const float* K  = (const float*)d_in[1];
    const float* V  = (const float*)d_in[2];
    const float* WQ = (const float*)d_in[3];
    const float* WK = (const float*)d_in[4];
    const float* WV = (const float*)d_in[5];
    const float* WO = (const float*)d_in[6];
    float* out = (float*)d_out;

    const int attn_smem = (NS / 2 * KCELL + NS / 2 * VCELL) * 4;   // 176KB
    cudaFuncSetAttribute(attn_kernel, cudaFuncAttributeMaxDynamicSharedMemorySize, attn_smem);

    prep_kernel<<<3 * ND * NCOL / 256, 256>>>(WQ, WK, WV);

    dim3 g1(NROW / 32, 1, 3);
    proj_kernel<<<g1, 128>>>(Q, K, V);

    dim3 g2(NS / 1024, NB * NH);
    attn_kernel<<<g2, 512, attn_smem>>>();

    dim3 g3(ND / 128, NROW / 32);
    outproj_kernel<<<g3, 128>>>(WO, out);
}

// round 7
// speedup vs baseline: 1.0854x; 1.0854x over previous
#include <cuda_runtime.h>
#include <math.h>

#define NB 4
#define NS 2048
#define ND 1024
#define NH 16
#define NDK 10
#define NDV 12
#define DP 12
#define NROW (NB*NS)          // 8192
#define NCOL (NH*DP)          // 192
#define KCELL 20              // 2 keys x 10 dims, pair-interleaved
#define VCELL 24              // 2 keys x 12 dims, pair-interleaved

// scratch (device globals: no allocation allowed)
__device__ float g_qp[NB*NH*NS*DP];          // q*(log2e/sqrt10), 12-stride, cols 0..9 valid
__device__ float g_ki[NB*NH*(NS/2)*KCELL];   // K pairs: cell[j] = (k_{2t}[j], k_{2t+1}[j])
__device__ float g_vi[NB*NH*(NS/2)*VCELL];   // V pairs: cell[j] = (v_{2t}[j], v_{2t+1}[j])
__device__ float g_heads[NROW*NCOL];         // concat heads [b*S+s][h*12+j]

typedef unsigned long long u64;

__device__ __forceinline__ u64 ffma2(u64 a, u64 b, u64 c) {
    u64 d; asm("fma.rn.f32x2 %0, %1, %2, %3;" : "=l"(d) : "l"(a), "l"(b), "l"(c)); return d;
}
__device__ __forceinline__ u64 fadd2(u64 a, u64 b) {
    u64 d; asm("add.rn.f32x2 %0, %1, %2;" : "=l"(d) : "l"(a), "l"(b)); return d;
}
__device__ __forceinline__ u64 pack2(float x, float y) {
    u64 r; asm("mov.b64 %0, {%1, %2};" : "=l"(r) : "f"(x), "f"(y)); return r;
}
__device__ __forceinline__ void unpack2(u64 v, float& x, float& y) {
    asm("mov.b64 {%0, %1}, %2;" : "=f"(x), "=f"(y) : "l"(v));
}
__device__ __forceinline__ float ex2f(float x) {
    float y; asm("ex2.approx.f32 %0, %1;" : "=f"(y) : "f"(x)); return y;
}

// ---------------------------------------------------------------------------
// Kernel 1: fused QKV projection (R3-proven layout), double-buffered.
// grid.z selects {Q,K,V}. CTA tile: 64 rows x 192 cols, BK=16.
// 256 threads = 8 warps; warp=8 rows (broadcast A), lane=1 of 32 colgroups.
// K and V outputs written pair-interleaved for the attention kernel.
// ---------------------------------------------------------------------------
__global__ __launch_bounds__(256, 2) void proj_kernel(
    const float* __restrict__ Q, const float* __restrict__ K, const float* __restrict__ V,
    const float* __restrict__ WQ, const float* __restrict__ WK, const float* __restrict__ WV)
{
    __shared__ u64 As2[16][64];       // [kk][row], value duplicated in both halves
    __shared__ float Bs[16 * NCOL];   // [kk][col] flat

    const float* X; const float* W; int dout;
    if (blockIdx.z == 0)      { X = Q; W = WQ; dout = NDK; }
    else if (blockIdx.z == 1) { X = K; W = WK; dout = NDK; }
    else                      { X = V; W = WV; dout = NDV; }

    const int tid = threadIdx.x;
    const int ty = tid >> 5, tx = tid & 31;      // 8 rowgroups x 32 colgroups
    const int row0 = blockIdx.x * 64;
    const int lr = tid >> 2, lseg = tid & 3;

    // hoisted B-tile load indexing
    int woff[12], soff[12]; bool vmask[12];
    #pragma unroll
    for (int i = 0; i < 12; i++) {
        int e = tid + i * 256;            // 3072 = 16*192 elements
        int kk = e / NCOL, c = e - kk * NCOL;
        int h = c / DP, j = c - h * DP;
        woff[i]  = (h * ND + kk) * dout + j;
        soff[i]  = kk * NCOL + c;
        vmask[i] = (j < dout);
    }
    const float* aptr = X + (size_t)(row0 + lr) * ND + lseg * 4;

    float4 areg = *(const float4*)aptr;
    float breg[12];
    #pragma unroll
    for (int i = 0; i < 12; i++) breg[i] = vmask[i] ? W[woff[i]] : 0.0f;

    u64 acc[8][3];
    #pragma unroll
    for (int r = 0; r < 8; r++)
        #pragma unroll
        for (int j = 0; j < 3; j++) acc[r][j] = 0ull;

    for (int t = 0; t < ND / 16; t++) {
        As2[lseg * 4 + 0][lr] = pack2(areg.x, areg.x);
        As2[lseg * 4 + 1][lr] = pack2(areg.y, areg.y);
        As2[lseg * 4 + 2][lr] = pack2(areg.z, areg.z);
        As2[lseg * 4 + 3][lr] = pack2(areg.w, areg.w);
        #pragma unroll
        for (int i = 0; i < 12; i++) Bs[soff[i]] = breg[i];
        __syncthreads();

        if (t < ND / 16 - 1) {
            areg = *(const float4*)(aptr + (t + 1) * 16);
            int kadd = (t + 1) * 16 * dout;
            #pragma unroll
            for (int i = 0; i < 12; i++) breg[i] = vmask[i] ? W[woff[i] + kadd] : 0.0f;
        }

        #pragma unroll
        for (int kk = 0; kk < 16; kk++) {
            const u64* bp = (const u64*)&Bs[kk * NCOL + tx * 6];
            u64 b0 = bp[0], b1 = bp[1], b2 = bp[2];
            #pragma unroll
            for (int r = 0; r < 8; r++) {
                u64 a = As2[kk][ty * 8 + r];
                acc[r][0] = ffma2(a, b0, acc[r][0]);
                acc[r][1] = ffma2(a, b1, acc[r][1]);
                acc[r][2] = ffma2(a, b2, acc[r][2]);
            }
        }
        __syncthreads();
    }

    // epilogue: thread owns 8 even-aligned rows (ty*8+r), f32 cols [tx*6, tx*6+6)
    float o[8][6];
    #pragma unroll
    for (int r = 0; r < 8; r++)
        #pragma unroll
        for (int j = 0; j < 3; j++) unpack2(acc[r][j], o[r][2 * j], o[r][2 * j + 1]);

    const int h = tx >> 1, j0 = (tx & 1) * 6;
    const int grow0 = row0 + ty * 8;
    const int b = grow0 >> 11, s0 = grow0 & 2047;
    const int bh = b * NH + h;

    if (blockIdx.z == 0) {              // Q: scale by log2e/sqrt(10), store dims < 10
        const float oscale = 1.4426950408889634f * rsqrtf((float)NDK);
        #pragma unroll
        for (int r = 0; r < 8; r++) {
            float* dst = g_qp + ((size_t)bh * NS + s0 + r) * DP + j0;
            #pragma unroll
            for (int jj = 0; jj < 6; jj += 2) {
                if (j0 + jj < NDK)
                    *(float2*)(dst + jj) = make_float2(o[r][jj] * oscale, o[r][jj + 1] * oscale);
            }
        }
    } else if (blockIdx.z == 1) {       // K: pair-interleaved cells (dims < 10)
        #pragma unroll
        for (int c = 0; c < 4; c++) {
            int s2 = (s0 >> 1) + c;
            u64* cell = (u64*)(g_ki + ((size_t)bh * (NS / 2) + s2) * KCELL);
            #pragma unroll
            for (int jj = 0; jj < 6; jj++) {
                int j = j0 + jj;
                if (j < NDK) cell[j] = pack2(o[2 * c][jj], o[2 * c + 1][jj]);
            }
        }
    } else {                            // V: pair-interleaved cells (all 12 dims)
        #pragma unroll
        for (int c = 0; c < 4; c++) {
            int s2 = (s0 >> 1) + c;
            u64* cell = (u64*)(g_vi + ((size_t)bh * (NS / 2) + s2) * VCELL);
            #pragma unroll
            for (int jj = 0; jj < 6; jj++)
                cell[j0 + jj] = pack2(o[2 * c][jj], o[2 * c + 1][jj]);
        }
    }
}

// ---------------------------------------------------------------------------
// Kernel 2: attention. grid (2, 64), 512 threads; 2 q rows/thread.
// K (80KB) + V (96KB) pair-interleaved in smem; key-in-lane accumulators so
// exp2 outputs pair directly into the FFMA2 operand (no duplication MOVs).
// No online max (scores bounded ~|18| << exp2 range).
// ---------------------------------------------------------------------------
__global__ __launch_bounds__(512, 1) void attn_kernel()
{
    extern __shared__ float smem[];
    float* ksf = smem;                       // [1024][20]
    float* vsf = smem + 1024 * KCELL;        // [1024][24]
    const int bh = blockIdx.y;
    const int tid = threadIdx.x;

    {
        const float4* ks = (const float4*)(g_ki + (size_t)bh * (NS / 2) * KCELL);
        float4* kd = (float4*)ksf;
        for (int i = tid; i < NS / 2 * KCELL / 4; i += 512) kd[i] = ks[i];
        const float4* vsrc = (const float4*)(g_vi + (size_t)bh * (NS / 2) * VCELL);
        float4* vd = (float4*)vsf;
        for (int i = tid; i < NS / 2 * VCELL / 4; i += 512) vd[i] = vsrc[i];
    }
    __syncthreads();

    const int rowA = blockIdx.x * 1024 + tid;
    const int rowB = rowA + 512;

    u64 qA[10], qB[10];
    {
        const float* qr = g_qp + ((size_t)bh * NS + rowA) * DP;
        float4 a = *(const float4*)qr, b4 = *(const float4*)(qr + 4);
        float2 c = *(const float2*)(qr + 8);
        float q[10] = { a.x, a.y, a.z, a.w, b4.x, b4.y, b4.z, b4.w, c.x, c.y };
        #pragma unroll
        for (int i = 0; i < 10; i++) qA[i] = pack2(q[i], q[i]);
    }
    {
        const float* qr = g_qp + ((size_t)bh * NS + rowB) * DP;
        float4 a = *(const float4*)qr, b4 = *(const float4*)(qr + 4);
        float2 c = *(const float2*)(qr + 8);
        float q[10] = { a.x, a.y, a.z, a.w, b4.x, b4.y, b4.z, b4.w, c.x, c.y };
        #pragma unroll
        for (int i = 0; i < 10; i++) qB[i] = pack2(q[i], q[i]);
    }

    u64 accA[12], accB[12];
    #pragma unroll
    for (int j = 0; j < 12; j++) { accA[j] = 0ull; accB[j] = 0ull; }
    u64 lA = 0ull, lB = 0ull;

    const ulonglong2* k2 = (const ulonglong2*)ksf;
    const ulonglong2* v2 = (const ulonglong2*)vsf;

    #pragma unroll 2
    for (int t2 = 0; t2 < NS / 2; t2++) {
        const ulonglong2* kc = k2 + (size_t)t2 * 5;
        ulonglong2 K0 = kc[0], K1 = kc[1], K2 = kc[2], K3 = kc[3], K4 = kc[4];

        // split dependency chains (5 deep each)
        u64 sA1 = 0ull, sA2 = 0ull, sB1 = 0ull, sB2 = 0ull;
        sA1 = ffma2(qA[0], K0.x, sA1);  sB1 = ffma2(qB[0], K0.x, sB1);
        sA2 = ffma2(qA[1], K0.y, sA2);  sB2 = ffma2(qB[1], K0.y, sB2);
        sA1 = ffma2(qA[2], K1.x, sA1);  sB1 = ffma2(qB[2], K1.x, sB1);
        sA2 = ffma2(qA[3], K1.y, sA2);  sB2 = ffma2(qB[3], K1.y, sB2);
        sA1 = ffma2(qA[4], K2.x, sA1);  sB1 = ffma2(qB[4], K2.x, sB1);
        sA2 = ffma2(qA[5], K2.y, sA2);  sB2 = ffma2(qB[5], K2.y, sB2);
        sA1 = ffma2(qA[6], K3.x, sA1);  sB1 = ffma2(qB[6], K3.x, sB1);
        sA2 = ffma2(qA[7], K3.y, sA2);  sB2 = ffma2(qB[7], K3.y, sB2);
        sA1 = ffma2(qA[8], K4.x, sA1);  sB1 = ffma2(qB[8], K4.x, sB1);
        sA2 = ffma2(qA[9], K4.y, sA2);  sB2 = ffma2(qB[9], K4.y, sB2);

        float s0A, s1A, s0B, s1B;
        unpack2(fadd2(sA1, sA2), s0A, s1A);
        unpack2(fadd2(sB1, sB2), s0B, s1B);
        u64 ppA = pack2(ex2f(s0A), ex2f(s1A));   // (p_even, p_odd)
        u64 ppB = pack2(ex2f(s0B), ex2f(s1B));
        lA = fadd2(lA, ppA);
        lB = fadd2(lB, ppB);

        const ulonglong2* vc = v2 + (size_t)t2 * 6;
        {
            ulonglong2 V0 = vc[0], V1 = vc[1], V2 = vc[2];
            accA[0] = ffma2(ppA, V0.x, accA[0]);  accB[0] = ffma2(ppB, V0.x, accB[0]);
            accA[1] = ffma2(ppA, V0.y, accA[1]);  accB[1] = ffma2(ppB, V0.y, accB[1]);
            accA[2] = ffma2(ppA, V1.x, accA[2]);  accB[2] = ffma2(ppB, V1.x, accB[2]);
            accA[3] = ffma2(ppA, V1.y, accA[3]);  accB[3] = ffma2(ppB, V1.y, accB[3]);
            accA[4] = ffma2(ppA, V2.x, accA[4]);  accB[4] = ffma2(ppB, V2.x, accB[4]);
            accA[5] = ffma2(ppA, V2.y, accA[5]);  accB[5] = ffma2(ppB, V2.y, accB[5]);
        }
        {
            ulonglong2 V3 = vc[3], V4 = vc[4], V5 = vc[5];
            accA[6]  = ffma2(ppA, V3.x, accA[6]);   accB[6]  = ffma2(ppB, V3.x, accB[6]);
            accA[7]  = ffma2(ppA, V3.y, accA[7]);   accB[7]  = ffma2(ppB, V3.y, accB[7]);
            accA[8]  = ffma2(ppA, V4.x, accA[8]);   accB[8]  = ffma2(ppB, V4.x, accB[8]);
            accA[9]  = ffma2(ppA, V4.y, accA[9]);   accB[9]  = ffma2(ppB, V4.y, accB[9]);
            accA[10] = ffma2(ppA, V5.x, accA[10]);  accB[10] = ffma2(ppB, V5.x, accB[10]);
            accA[11] = ffma2(ppA, V5.y, accA[11]);  accB[11] = ffma2(ppB, V5.y, accB[11]);
        }
    }

    const int b = bh >> 4, h = bh & 15;
    {
        float la0, la1; unpack2(lA, la0, la1);
        float inv = 1.0f / (la0 + la1);
        float o[12];
        #pragma unroll
        for (int j = 0; j < 12; j++) { float e, od; unpack2(accA[j], e, od); o[j] = (e + od) * inv; }
        float* dst = g_heads + (size_t)(b * NS + rowA) * NCOL + h * NDV;
        *(float4*)(dst + 0) = make_float4(o[0], o[1], o[2],  o[3]);
        *(float4*)(dst + 4) = make_float4(o[4], o[5], o[6],  o[7]);
        *(float4*)(dst + 8) = make_float4(o[8], o[9], o[10], o[11]);
    }
    {
        float lb0, lb1; unpack2(lB, lb0, lb1);
        float inv = 1.0f / (lb0 + lb1);
        float o[12];
        #pragma unroll
        for (int j = 0; j < 12; j++) { float e, od; unpack2(accB[j], e, od); o[j] = (e + od) * inv; }
        float* dst = g_heads + (size_t)(b * NS + rowB) * NCOL + h * NDV;
        *(float4*)(dst + 0) = make_float4(o[0], o[1], o[2],  o[3]);
        *(float4*)(dst + 4) = make_float4(o[4], o[5], o[6],  o[7]);
        *(float4*)(dst + 8) = make_float4(o[8], o[9], o[10], o[11]);
    }
}

// ---------------------------------------------------------------------------
// Kernel 3: output projection (R3-proven layout), double-buffered.
// [8192,192] x [192,1024]. CTA tile 64 x 128, BK=16. 256 threads = 8x32;
// 8 rows x 4 cols each.
// ---------------------------------------------------------------------------
__global__ __launch_bounds__(256, 2) void outproj_kernel(
    const float* __restrict__ WO, float* __restrict__ out)
{
    __shared__ u64 As2[16][64];
    __shared__ float Bs[16 * 128];
    const int tid = threadIdx.x;
    const int tyy = tid >> 5, txx = tid & 31;
    const int row0 = blockIdx.y * 64;
    const int col0 = blockIdx.x * 128;
    const int lr = tid >> 2, lseg = tid & 3;

    int woff[8], soff[8];
    #pragma unroll
    for (int i = 0; i < 8; i++) {
        int e = i * 256 + tid;
        int kk = e >> 7, c = e & 127;
        woff[i] = kk * ND + col0 + c;
        soff[i] = kk * 128 + c;
    }
    const float* aptr = g_heads + (size_t)(row0 + lr) * NCOL + lseg * 4;

    float4 areg = *(const float4*)aptr;
    float breg[8];
    #pragma unroll
    for (int i = 0; i < 8; i++) breg[i] = WO[woff[i]];

    u64 acc[8][2];
    #pragma unroll
    for (int r = 0; r < 8; r++) { acc[r][0] = 0ull; acc[r][1] = 0ull; }

    const int NT = NCOL / 16;
    for (int t = 0; t < NT; t++) {
        As2[lseg * 4 + 0][lr] = pack2(areg.x, areg.x);
        As2[lseg * 4 + 1][lr] = pack2(areg.y, areg.y);
        As2[lseg * 4 + 2][lr] = pack2(areg.z, areg.z);
        As2[lseg * 4 + 3][lr] = pack2(areg.w, areg.w);
        #pragma unroll
        for (int i = 0; i < 8; i++) Bs[soff[i]] = breg[i];
        __syncthreads();

        if (t < NT - 1) {
            areg = *(const float4*)(aptr + (t + 1) * 16);
            int kadd = (t + 1) * 16 * ND;
            #pragma unroll
            for (int i = 0; i < 8; i++) breg[i] = WO[woff[i] + kadd];
        }

        #pragma unroll
        for (int kk = 0; kk < 16; kk++) {
            ulonglong2 bv = *(const ulonglong2*)&Bs[kk * 128 + txx * 4];
            #pragma unroll
            for (int r = 0; r < 8; r++) {
                u64 a = As2[kk][tyy * 8 + r];
                acc[r][0] = ffma2(a, bv.x, acc[r][0]);
                acc[r][1] = ffma2(a, bv.y, acc[r][1]);
            }
        }
        __syncthreads();
    }

    #pragma unroll
    for (int r = 0; r < 8; r++) {
        float o[4];
        unpack2(acc[r][0], o[0], o[1]);
        unpack2(acc[r][1], o[2], o[3]);
        float* dst = out + (size_t)(row0 + tyy * 8 + r) * ND + col0 + txx * 4;
        *(float4*)dst = make_float4(o[0], o[1], o[2], o[3]);
    }
}

// ---------------------------------------------------------------------------
extern "C" void kernel_launch(void* const* d_in, const int* in_sizes, int n_in,
                              void* d_out, int out_size)
{
    const float* Q  = (const float*)d_in[0];
    const float* K  = (const float*)d_in[1];
    const float* V  = (const float*)d_in[2];
    const float* WQ = (const float*)d_in[3];
    const float* WK = (const float*)d_in[4];
    const float* WV = (const float*)d_in[5];
    const float* WO = (const float*)d_in[6];
    float* out = (float*)d_out;

    const int attn_smem = (NS / 2 * KCELL + NS / 2 * VCELL) * 4;   // 176KB
    cudaFuncSetAttribute(attn_kernel, cudaFuncAttributeMaxDynamicSharedMemorySize, attn_smem);

    dim3 g1(NROW / 64, 1, 3);
    proj_kernel<<<g1, 256>>>(Q, K, V, WQ, WK, WV);

    dim3 g2(NS / 1024, NB * NH);
    attn_kernel<<<g2, 512, attn_smem>>>();

    dim3 g3(ND / 128, NROW / 64);
    outproj_kernel<<<g3, 256>>>(WO, out);
}

// round 10
// speedup vs baseline: 1.0926x; 1.0066x over previous
#include <cuda_runtime.h>
#include <math.h>

#define NB 4
#define NS 2048
#define ND 1024
#define NH 16
#define NDK 10
#define NDV 12
#define DP 12
#define NROW (NB*NS)          // 8192
#define NCOL (NH*DP)          // 192
#define KCELL 20              // 2 keys x 10 dims, pair-interleaved
#define VCELL 24              // 2 keys x 12 dims, pair-interleaved

// scratch (device globals: no allocation allowed)
__device__ float g_qp[NB*NH*NS*DP];          // q*(log2e/sqrt10), 12-stride, cols 0..9 valid
__device__ float g_ki[NB*NH*(NS/2)*KCELL];   // K pairs: cell[j] = (k_{2t}[j], k_{2t+1}[j])
__device__ float g_vi[NB*NH*(NS/2)*VCELL];   // V pairs: cell[j] = (v_{2t}[j], v_{2t+1}[j])
__device__ float g_heads[NROW*NCOL];         // concat heads [b*S+s][h*12+j]

typedef unsigned long long u64;

__device__ __forceinline__ u64 ffma2(u64 a, u64 b, u64 c) {
    u64 d; asm("fma.rn.f32x2 %0, %1, %2, %3;" : "=l"(d) : "l"(a), "l"(b), "l"(c)); return d;
}
__device__ __forceinline__ u64 fadd2(u64 a, u64 b) {
    u64 d; asm("add.rn.f32x2 %0, %1, %2;" : "=l"(d) : "l"(a), "l"(b)); return d;
}
__device__ __forceinline__ u64 pack2(float x, float y) {
    u64 r; asm("mov.b64 %0, {%1, %2};" : "=l"(r) : "f"(x), "f"(y)); return r;
}
__device__ __forceinline__ void unpack2(u64 v, float& x, float& y) {
    asm("mov.b64 {%0, %1}, %2;" : "=f"(x), "=f"(y) : "l"(v));
}
__device__ __forceinline__ float ex2f(float x) {
    float y; asm("ex2.approx.f32 %0, %1;" : "=f"(y) : "f"(x)); return y;
}

// ---------------------------------------------------------------------------
// Kernel 1: fused QKV projection, double-buffered. FFMA-bound warp geometry:
// warp = all 64 rows x 12 u64cols (2 heads); lane = 2 consecutive rows.
// Per warp-kk: A = 1 LDS.128/thread (contig, 4 wf), B = 6 LDS.128 broadcast
// (6 wf), 24 FFMA2. Per-SM: 160 wf < 192 FFMA-cyc -> FFMA-bound.
// Staging (smem image + prefetch) identical to the proven R3 code.
// ---------------------------------------------------------------------------
__global__ __launch_bounds__(256, 2) void proj_kernel(
    const float* __restrict__ Q, const float* __restrict__ K, const float* __restrict__ V,
    const float* __restrict__ WQ, const float* __restrict__ WK, const float* __restrict__ WV)
{
    __shared__ u64 As2[16][64];       // [kk][row], value duplicated in both halves
    __shared__ float Bs[16 * NCOL];   // [kk][col] flat

    const float* X; const float* W; int dout;
    if (blockIdx.z == 0)      { X = Q; W = WQ; dout = NDK; }
    else if (blockIdx.z == 1) { X = K; W = WK; dout = NDK; }
    else                      { X = V; W = WV; dout = NDV; }

    const int tid = threadIdx.x;
    const int warp = tid >> 5, lane = tid & 31;
    const int row0 = blockIdx.x * 64;
    const int lr = tid >> 2, lseg = tid & 3;

    // hoisted B-tile load indexing
    int woff[12], soff[12]; bool vmask[12];
    #pragma unroll
    for (int i = 0; i < 12; i++) {
        int e = tid + i * 256;            // 3072 = 16*192 elements
        int kk = e / NCOL, c = e - kk * NCOL;
        int h = c / DP, j = c - h * DP;
        woff[i]  = (h * ND + kk) * dout + j;
        soff[i]  = kk * NCOL + c;
        vmask[i] = (j < dout);
    }
    const float* aptr = X + (size_t)(row0 + lr) * ND + lseg * 4;

    float4 areg = *(const float4*)aptr;
    float breg[12];
    #pragma unroll
    for (int i = 0; i < 12; i++) breg[i] = vmask[i] ? W[woff[i]] : 0.0f;

    u64 acc[2][12];
    #pragma unroll
    for (int r = 0; r < 2; r++)
        #pragma unroll
        for (int j = 0; j < 12; j++) acc[r][j] = 0ull;

    for (int t = 0; t < ND / 16; t++) {
        As2[lseg * 4 + 0][lr] = pack2(areg.x, areg.x);
        As2[lseg * 4 + 1][lr] = pack2(areg.y, areg.y);
        As2[lseg * 4 + 2][lr] = pack2(areg.z, areg.z);
        As2[lseg * 4 + 3][lr] = pack2(areg.w, areg.w);
        #pragma unroll
        for (int i = 0; i < 12; i++) Bs[soff[i]] = breg[i];
        __syncthreads();

        if (t < ND / 16 - 1) {
            areg = *(const float4*)(aptr + (t + 1) * 16);
            int kadd = (t + 1) * 16 * dout;
            #pragma unroll
            for (int i = 0; i < 12; i++) breg[i] = vmask[i] ? W[woff[i] + kadd] : 0.0f;
        }

        #pragma unroll
        for (int kk = 0; kk < 16; kk++) {
            // A: rows 2*lane, 2*lane+1 (contiguous 16B across warp)
            ulonglong2 a = *(const ulonglong2*)&As2[kk][2 * lane];
            // B: 12 u64 cols for this warp (uniform address -> broadcast)
            const ulonglong2* bp = (const ulonglong2*)&Bs[kk * NCOL + warp * 24];
            ulonglong2 b0 = bp[0], b1 = bp[1], b2 = bp[2];
            ulonglong2 b3 = bp[3], b4 = bp[4], b5 = bp[5];
            u64 bv[12] = { b0.x, b0.y, b1.x, b1.y, b2.x, b2.y,
                           b3.x, b3.y, b4.x, b4.y, b5.x, b5.y };
            #pragma unroll
            for (int j = 0; j < 12; j++) {
                acc[0][j] = ffma2(a.x, bv[j], acc[0][j]);
                acc[1][j] = ffma2(a.y, bv[j], acc[1][j]);
            }
        }
        __syncthreads();
    }

    // epilogue: thread owns rows (row0+2*lane, +1), f32 cols [warp*24, warp*24+24)
    float o[2][24];
    #pragma unroll
    for (int r = 0; r < 2; r++)
        #pragma unroll
        for (int j = 0; j < 12; j++) unpack2(acc[r][j], o[r][2 * j], o[r][2 * j + 1]);

    const int grow0 = row0 + 2 * lane;
    const int b = grow0 >> 11, s0 = grow0 & 2047;   // s0 even

    if (blockIdx.z == 0) {              // Q: scale by log2e/sqrt(10), store dims < 10
        const float oscale = 1.4426950408889634f * rsqrtf((float)NDK);
        #pragma unroll
        for (int r = 0; r < 2; r++) {
            #pragma unroll
            for (int hh = 0; hh < 2; hh++) {
                const int h = warp * 2 + hh;
                float* dst = g_qp + ((size_t)(b * NH + h) * NS + s0 + r) * DP;
                const float* src = &o[r][hh * 12];
                *(float4*)(dst + 0) = make_float4(src[0] * oscale, src[1] * oscale,
                                                  src[2] * oscale, src[3] * oscale);
                *(float4*)(dst + 4) = make_float4(src[4] * oscale, src[5] * oscale,
                                                  src[6] * oscale, src[7] * oscale);
                *(float2*)(dst + 8) = make_float2(src[8] * oscale, src[9] * oscale);
            }
        }
    } else if (blockIdx.z == 1) {       // K: pair-interleaved cells (dims < 10)
        const int s2 = s0 >> 1;
        #pragma unroll
        for (int hh = 0; hh < 2; hh++) {
            const int h = warp * 2 + hh;
            u64* cell = (u64*)(g_ki + ((size_t)(b * NH + h) * (NS / 2) + s2) * KCELL);
            #pragma unroll
            for (int j = 0; j < 10; j += 2) {
                ulonglong2 v;
                v.x = pack2(o[0][hh * 12 + j],     o[1][hh * 12 + j]);
                v.y = pack2(o[0][hh * 12 + j + 1], o[1][hh * 12 + j + 1]);
                *(ulonglong2*)(cell + j) = v;
            }
        }
    } else {                            // V: pair-interleaved cells (all 12 dims)
        const int s2 = s0 >> 1;
        #pragma unroll
        for (int hh = 0; hh < 2; hh++) {
            const int h = warp * 2 + hh;
            u64* cell = (u64*)(g_vi + ((size_t)(b * NH + h) * (NS / 2) + s2) * VCELL);
            #pragma unroll
            for (int j = 0; j < 12; j += 2) {
                ulonglong2 v;
                v.x = pack2(o[0][hh * 12 + j],     o[1][hh * 12 + j]);
                v.y = pack2(o[0][hh * 12 + j + 1], o[1][hh * 12 + j + 1]);
                *(ulonglong2*)(cell + j) = v;
            }
        }
    }
}

// ---------------------------------------------------------------------------
// Kernel 2: attention. grid (2, 64), 512 threads; 2 q rows/thread.
// K (80KB) + V (96KB) pair-interleaved in smem; key-in-lane accumulators.
// No online max (scores bounded ~|18| << exp2 range).
// ---------------------------------------------------------------------------
__global__ __launch_bounds__(512, 1) void attn_kernel()
{
    extern __shared__ float smem[];
    float* ksf = smem;                       // [1024][20]
    float* vsf = smem + 1024 * KCELL;        // [1024][24]
    const int bh = blockIdx.y;
    const int tid = threadIdx.x;

    {
        const float4* ks = (const float4*)(g_ki + (size_t)bh * (NS / 2) * KCELL);
        float4* kd = (float4*)ksf;
        for (int i = tid; i < NS / 2 * KCELL / 4; i += 512) kd[i] = ks[i];
        const float4* vsrc = (const float4*)(g_vi + (size_t)bh * (NS / 2) * VCELL);
        float4* vd = (float4*)vsf;
        for (int i = tid; i < NS / 2 * VCELL / 4; i += 512) vd[i] = vsrc[i];
    }
    __syncthreads();

    const int rowA = blockIdx.x * 1024 + tid;
    const int rowB = rowA + 512;

    u64 qA[10], qB[10];
    {
        const float* qr = g_qp + ((size_t)bh * NS + rowA) * DP;
        float4 a = *(const float4*)qr, b4 = *(const float4*)(qr + 4);
        float2 c = *(const float2*)(qr + 8);
        float q[10] = { a.x, a.y, a.z, a.w, b4.x, b4.y, b4.z, b4.w, c.x, c.y };
        #pragma unroll
        for (int i = 0; i < 10; i++) qA[i] = pack2(q[i], q[i]);
    }
    {
        const float* qr = g_qp + ((size_t)bh * NS + rowB) * DP;
        float4 a = *(const float4*)qr, b4 = *(const float4*)(qr + 4);
        float2 c = *(const float2*)(qr + 8);
        float q[10] = { a.x, a.y, a.z, a.w, b4.x, b4.y, b4.z, b4.w, c.x, c.y };
        #pragma unroll
        for (int i = 0; i < 10; i++) qB[i] = pack2(q[i], q[i]);
    }

    u64 accA[12], accB[12];
    #pragma unroll
    for (int j = 0; j < 12; j++) { accA[j] = 0ull; accB[j] = 0ull; }
    u64 lA = 0ull, lB = 0ull;

    const ulonglong2* k2 = (const ulonglong2*)ksf;
    const ulonglong2* v2 = (const ulonglong2*)vsf;

    #pragma unroll 2
    for (int t2 = 0; t2 < NS / 2; t2++) {
        const ulonglong2* kc = k2 + (size_t)t2 * 5;
        ulonglong2 K0 = kc[0], K1 = kc[1], K2 = kc[2], K3 = kc[3], K4 = kc[4];

        u64 sA1 = 0ull, sA2 = 0ull, sB1 = 0ull, sB2 = 0ull;
        sA1 = ffma2(qA[0], K0.x, sA1);  sB1 = ffma2(qB[0], K0.x, sB1);
        sA2 = ffma2(qA[1], K0.y, sA2);  sB2 = ffma2(qB[1], K0.y, sB2);
        sA1 = ffma2(qA[2], K1.x, sA1);  sB1 = ffma2(qB[2], K1.x, sB1);
        sA2 = ffma2(qA[3], K1.y, sA2);  sB2 = ffma2(qB[3], K1.y, sB2);
        sA1 = ffma2(qA[4], K2.x, sA1);  sB1 = ffma2(qB[4], K2.x, sB1);
        sA2 = ffma2(qA[5], K2.y, sA2);  sB2 = ffma2(qB[5], K2.y, sB2);
        sA1 = ffma2(qA[6], K3.x, sA1);  sB1 = ffma2(qB[6], K3.x, sB1);
        sA2 = ffma2(qA[7], K3.y, sA2);  sB2 = ffma2(qB[7], K3.y, sB2);
        sA1 = ffma2(qA[8], K4.x, sA1);  sB1 = ffma2(qB[8], K4.x, sB1);
        sA2 = ffma2(qA[9], K4.y, sA2);  sB2 = ffma2(qB[9], K4.y, sB2);

        float s0A, s1A, s0B, s1B;
        unpack2(fadd2(sA1, sA2), s0A, s1A);
        unpack2(fadd2(sB1, sB2), s0B, s1B);
        u64 ppA = pack2(ex2f(s0A), ex2f(s1A));   // (p_even, p_odd)
        u64 ppB = pack2(ex2f(s0B), ex2f(s1B));
        lA = fadd2(lA, ppA);
        lB = fadd2(lB, ppB);

        const ulonglong2* vc = v2 + (size_t)t2 * 6;
        {
            ulonglong2 V0 = vc[0], V1 = vc[1], V2 = vc[2];
            accA[0] = ffma2(ppA, V0.x, accA[0]);  accB[0] = ffma2(ppB, V0.x, accB[0]);
            accA[1] = ffma2(ppA, V0.y, accA[1]);  accB[1] = ffma2(ppB, V0.y, accB[1]);
            accA[2] = ffma2(ppA, V1.x, accA[2]);  accB[2] = ffma2(ppB, V1.x, accB[2]);
            accA[3] = ffma2(ppA, V1.y, accA[3]);  accB[3] = ffma2(ppB, V1.y, accB[3]);
            accA[4] = ffma2(ppA, V2.x, accA[4]);  accB[4] = ffma2(ppB, V2.x, accB[4]);
            accA[5] = ffma2(ppA, V2.y, accA[5]);  accB[5] = ffma2(ppB, V2.y, accB[5]);
        }
        {
            ulonglong2 V3 = vc[3], V4 = vc[4], V5 = vc[5];
            accA[6]  = ffma2(ppA, V3.x, accA[6]);   accB[6]  = ffma2(ppB, V3.x, accB[6]);
            accA[7]  = ffma2(ppA, V3.y, accA[7]);   accB[7]  = ffma2(ppB, V3.y, accB[7]);
            accA[8]  = ffma2(ppA, V4.x, accA[8]);   accB[8]  = ffma2(ppB, V4.x, accB[8]);
            accA[9]  = ffma2(ppA, V4.y, accA[9]);   accB[9]  = ffma2(ppB, V4.y, accB[9]);
            accA[10] = ffma2(ppA, V5.x, accA[10]);  accB[10] = ffma2(ppB, V5.x, accB[10]);
            accA[11] = ffma2(ppA, V5.y, accA[11]);  accB[11] = ffma2(ppB, V5.y, accB[11]);
        }
    }

    const int b = bh >> 4, h = bh & 15;
    {
        float la0, la1; unpack2(lA, la0, la1);
        float inv = 1.0f / (la0 + la1);
        float o[12];
        #pragma unroll
        for (int j = 0; j < 12; j++) { float e, od; unpack2(accA[j], e, od); o[j] = (e + od) * inv; }
        float* dst = g_heads + (size_t)(b * NS + rowA) * NCOL + h * NDV;
        *(float4*)(dst + 0) = make_float4(o[0], o[1], o[2],  o[3]);
        *(float4*)(dst + 4) = make_float4(o[4], o[5], o[6],  o[7]);
        *(float4*)(dst + 8) = make_float4(o[8], o[9], o[10], o[11]);
    }
    {
        float lb0, lb1; unpack2(lB, lb0, lb1);
        float inv = 1.0f / (lb0 + lb1);
        float o[12];
        #pragma unroll
        for (int j = 0; j < 12; j++) { float e, od; unpack2(accB[j], e, od); o[j] = (e + od) * inv; }
        float* dst = g_heads + (size_t)(b * NS + rowB) * NCOL + h * NDV;
        *(float4*)(dst + 0) = make_float4(o[0], o[1], o[2],  o[3]);
        *(float4*)(dst + 4) = make_float4(o[4], o[5], o[6],  o[7]);
        *(float4*)(dst + 8) = make_float4(o[8], o[9], o[10], o[11]);
    }
}

// ---------------------------------------------------------------------------
// Kernel 3: output projection (R3-proven layout), double-buffered.
// [8192,192] x [192,1024]. CTA tile 64 x 128, BK=16. 256 threads = 8x32;
// 8 rows x 4 cols each.
// ---------------------------------------------------------------------------
__global__ __launch_bounds__(256, 2) void outproj_kernel(
    const float* __restrict__ WO, float* __restrict__ out)
{
    __shared__ u64 As2[16][64];
    __shared__ float Bs[16 * 128];
    const int tid = threadIdx.x;
    const int tyy = tid >> 5, txx = tid & 31;
    const int row0 = blockIdx.y * 64;
    const int col0 = blockIdx.x * 128;
    const int lr = tid >> 2, lseg = tid & 3;

    int woff[8], soff[8];
    #pragma unroll
    for (int i = 0; i < 8; i++) {
        int e = i * 256 + tid;
        int kk = e >> 7, c = e & 127;
        woff[i] = kk * ND + col0 + c;
        soff[i] = kk * 128 + c;
    }
    const float* aptr = g_heads + (size_t)(row0 + lr) * NCOL + lseg * 4;

    float4 areg = *(const float4*)aptr;
    float breg[8];
    #pragma unroll
    for (int i = 0; i < 8; i++) breg[i] = WO[woff[i]];

    u64 acc[8][2];
    #pragma unroll
    for (int r = 0; r < 8; r++) { acc[r][0] = 0ull; acc[r][1] = 0ull; }

    const int NT = NCOL / 16;
    for (int t = 0; t < NT; t++) {
        As2[lseg * 4 + 0][lr] = pack2(areg.x, areg.x);
        As2[lseg * 4 + 1][lr] = pack2(areg.y, areg.y);
        As2[lseg * 4 + 2][lr] = pack2(areg.z, areg.z);
        As2[lseg * 4 + 3][lr] = pack2(areg.w, areg.w);
        #pragma unroll
        for (int i = 0; i < 8; i++) Bs[soff[i]] = breg[i];
        __syncthreads();

        if (t < NT - 1) {
            areg = *(const float4*)(aptr + (t + 1) * 16);
            int kadd = (t + 1) * 16 * ND;
            #pragma unroll
            for (int i = 0; i < 8; i++) breg[i] = WO[woff[i] + kadd];
        }

        #pragma unroll
        for (int kk = 0; kk < 16; kk++) {
            ulonglong2 bv = *(const ulonglong2*)&Bs[kk * 128 + txx * 4];
            #pragma unroll
            for (int r = 0; r < 8; r++) {
                u64 a = As2[kk][tyy * 8 + r];
                acc[r][0] = ffma2(a, bv.x, acc[r][0]);
                acc[r][1] = ffma2(a, bv.y, acc[r][1]);
            }
        }
        __syncthreads();
    }

    #pragma unroll
    for (int r = 0; r < 8; r++) {
        float o[4];
        unpack2(acc[r][0], o[0], o[1]);
        unpack2(acc[r][1], o[2], o[3]);
        float* dst = out + (size_t)(row0 + tyy * 8 + r) * ND + col0 + txx * 4;
        *(float4*)dst = make_float4(o[0], o[1], o[2], o[3]);
    }
}

// ---------------------------------------------------------------------------
extern "C" void kernel_launch(void* const* d_in, const int* in_sizes, int n_in,
                              void* d_out, int out_size)
{
    const float* Q  = (const float*)d_in[0];
    const float* K  = (const float*)d_in[1];
    const float* V  = (const float*)d_in[2];
    const float* WQ = (const float*)d_in[3];
    const float* WK = (const float*)d_in[4];
    const float* WV = (const float*)d_in[5];
    const float* WO = (const float*)d_in[6];
    float* out = (float*)d_out;

    const int attn_smem = (NS / 2 * KCELL + NS / 2 * VCELL) * 4;   // 176KB
    cudaFuncSetAttribute(attn_kernel, cudaFuncAttributeMaxDynamicSharedMemorySize, attn_smem);

    dim3 g1(NROW / 64, 1, 3);
    proj_kernel<<<g1, 256>>>(Q, K, V, WQ, WK, WV);

    dim3 g2(NS / 1024, NB * NH);
    attn_kernel<<<g2, 512, attn_smem>>>();

    dim3 g3(ND / 128, NROW / 64);
    outproj_kernel<<<g3, 256>>>(WO, out);
}

// round 13
// speedup vs baseline: 1.1271x; 1.0316x over previous
#include <cuda_runtime.h>
#include <math.h>
#include <stdint.h>

#define NB 4
#define NS 2048
#define ND 1024
#define NH 16
#define NDK 10
#define NDV 12
#define DP 12
#define NROW (NB*NS)          // 8192
#define NCOL (NH*DP)          // 192
#define KCELL 20              // 2 keys x 10 dims, pair-interleaved
#define NFRAG (128*24*2*32)   // per-z B fragment plane size = 196608

// scratch (device globals: no allocation allowed)
__device__ unsigned int g_bhi[3*NFRAG];      // W tf32 hi, fragment-ordered, Q scale folded
__device__ unsigned int g_blo[3*NFRAG];      // W tf32 lo
__device__ float g_qp[NB*NH*NS*DP];          // q*(log2e/sqrt10), 12-stride, cols 0..9 valid
__device__ float g_ki[NB*NH*(NS/2)*KCELL];   // K pairs: cell[j] = (k_{2t}[j], k_{2t+1}[j])
__device__ float g_vp[NB*NH*NS*DP];          // v, straight 12-stride rows
__device__ float g_heads[NROW*NCOL];         // concat heads [b*S+s][h*12+j]

typedef unsigned long long u64;
typedef unsigned int u32;

__device__ __forceinline__ u64 ffma2(u64 a, u64 b, u64 c) {
    u64 d; asm("fma.rn.f32x2 %0, %1, %2, %3;" : "=l"(d) : "l"(a), "l"(b), "l"(c)); return d;
}
__device__ __forceinline__ u64 pack2(float x, float y) {
    u64 r; asm("mov.b64 %0, {%1, %2};" : "=l"(r) : "f"(x), "f"(y)); return r;
}
__device__ __forceinline__ void unpack2(u64 v, float& x, float& y) {
    asm("mov.b64 {%0, %1}, %2;" : "=f"(x), "=f"(y) : "l"(v));
}
__device__ __forceinline__ float ex2f(float x) {
    float y; asm("ex2.approx.f32 %0, %1;" : "=f"(y) : "f"(x)); return y;
}
__device__ __forceinline__ u32 tf32_of(float x) {
    u32 r; asm("cvt.rna.tf32.f32 %0, %1;" : "=r"(r) : "f"(x)); return r;
}
__device__ __forceinline__ void mma_tf32(float* c, const u32* a, u32 b0, u32 b1) {
    asm volatile(
        "mma.sync.aligned.m16n8k8.row.col.f32.tf32.tf32.f32 "
        "{%0,%1,%2,%3}, {%4,%5,%6,%7}, {%8,%9}, {%0,%1,%2,%3};"
        : "+f"(c[0]), "+f"(c[1]), "+f"(c[2]), "+f"(c[3])
        : "r"(a[0]), "r"(a[1]), "r"(a[2]), "r"(a[3]), "r"(b0), "r"(b1));
}

// ---------------------------------------------------------------------------
// Kernel 0: split weights into tf32 hi/lo planes, FRAGMENT-ORDERED for
// m16n8k8 B (col) fragments; zero-pad j>=dout; fold Q scale before split.
// Fragment addr: kt*1536 + nt*64 + r*32 + lane, lane = nr*4 + (kr&3), r = kr>>2.
// ---------------------------------------------------------------------------
__global__ __launch_bounds__(256) void prep_kernel(
    const float* __restrict__ WQ, const float* __restrict__ WK, const float* __restrict__ WV)
{
    int idx = blockIdx.x * 256 + threadIdx.x;     // < 3*1024*192
    int z = idx / (ND * NCOL);
    int rem = idx - z * ND * NCOL;
    int k = rem / NCOL, n = rem - k * NCOL;
    int h = n / DP, j = n - h * DP;
    const float* W = (z == 0) ? WQ : ((z == 1) ? WK : WV);
    int dout = (z == 2) ? NDV : NDK;
    float w = (j < dout) ? W[(h * ND + k) * dout + j] : 0.0f;
    if (z == 0) w *= 1.4426950408889634f * rsqrtf(10.0f);
    u32 hi = tf32_of(w);
    u32 lo = tf32_of(w - __uint_as_float(hi));
    int kt = k >> 3, kr = k & 7, nt = n >> 3, nr = n & 7;
    int addr = z * NFRAG + kt * 1536 + nt * 64 + (kr >> 2) * 32 + nr * 4 + (kr & 3);
    g_bhi[addr] = hi;
    g_blo[addr] = lo;
}

// ---------------------------------------------------------------------------
// Kernel 1: QKV projection via tf32 mma.sync, 3-way split.
// grid (64,1,3), 256 threads = 8 warps (4m x 2n). CTA 128x192, warp 32x96.
// A staged fp32 in smem (pad 36, conflict-free), hi/lo split in regs.
// Epilogue: frags -> smem Cs[128][196] -> proven global layouts.
// ---------------------------------------------------------------------------
#define PROJ_SMEM (128*196*4)   // 100352; A staging [128][36] overlaps

__global__ __launch_bounds__(256) void proj_mma_kernel(
    const float* __restrict__ Q, const float* __restrict__ K, const float* __restrict__ V)
{
    extern __shared__ float sm[];
    float* As = sm;                  // [128][36] during mainloop
    float* Cs = sm;                  // [128][196] during epilogue

    const int z = blockIdx.z;
    const float* X = (z == 0) ? Q : ((z == 1) ? K : V);
    const u32* Bhi = g_bhi + (size_t)z * NFRAG;
    const u32* Blo = g_blo + (size_t)z * NFRAG;

    const int tid = threadIdx.x;
    const int warp = tid >> 5, lane = tid & 31;
    const int wm = warp & 3, wn = warp >> 2;         // 4m x 2n
    const int g = lane >> 2, tig = lane & 3;
    const int row0 = blockIdx.x * 128;

    float acc[2][12][4];
    #pragma unroll
    for (int mt = 0; mt < 2; mt++)
        #pragma unroll
        for (int nt = 0; nt < 12; nt++)
            #pragma unroll
            for (int c = 0; c < 4; c++) acc[mt][nt][c] = 0.0f;

    for (int t = 0; t < ND / 32; t++) {
        // stage A chunk [128][32] fp32
        #pragma unroll
        for (int i = 0; i < 4; i++) {
            int f = tid + i * 256;          // float4 idx < 1024
            int row = f >> 3, seg = f & 7;
            float4 v = *(const float4*)(X + (size_t)(row0 + row) * ND + t * 32 + seg * 4);
            *(float4*)&As[row * 36 + seg * 4] = v;
        }
        __syncthreads();

        #pragma unroll
        for (int ks = 0; ks < 4; ks++) {
            const int kt = t * 4 + ks;
            // A fragments, both m-tiles, hi/lo
            u32 ahi[2][4], alo[2][4];
            #pragma unroll
            for (int mt = 0; mt < 2; mt++) {
                int rb = (wm * 32 + mt * 16 + g) * 36 + ks * 8 + tig;
                float a0 = As[rb];
                float a1 = As[rb + 8 * 36];
                float a2 = As[rb + 4];
                float a3 = As[rb + 8 * 36 + 4];
                float av[4] = { a0, a1, a2, a3 };
                #pragma unroll
                for (int i = 0; i < 4; i++) {
                    ahi[mt][i] = tf32_of(av[i]);
                    alo[mt][i] = tf32_of(av[i] - __uint_as_float(ahi[mt][i]));
                }
            }
            const u32* bh = Bhi + kt * 1536 + (wn * 12) * 64 + lane;
            const u32* bl = Blo + kt * 1536 + (wn * 12) * 64 + lane;
            #pragma unroll
            for (int half = 0; half < 2; half++) {
                u32 bh0[6], bh1[6], bl0[6], bl1[6];
                #pragma unroll
                for (int q6 = 0; q6 < 6; q6++) {
                    int off = (half * 6 + q6) * 64;
                    bh0[q6] = bh[off];       bh1[q6] = bh[off + 32];
                    bl0[q6] = bl[off];       bl1[q6] = bl[off + 32];
                }
                #pragma unroll
                for (int mt = 0; mt < 2; mt++)
                    #pragma unroll
                    for (int q6 = 0; q6 < 6; q6++) {
                        float* c = acc[mt][half * 6 + q6];
                        mma_tf32(c, ahi[mt], bh0[q6], bh1[q6]);
                        mma_tf32(c, ahi[mt], bl0[q6], bl1[q6]);
                        mma_tf32(c, alo[mt], bh0[q6], bh1[q6]);
                    }
            }
        }
        __syncthreads();
    }

    // ---- epilogue: fragments -> Cs ----
    #pragma unroll
    for (int mt = 0; mt < 2; mt++)
        #pragma unroll
        for (int nt = 0; nt < 12; nt++) {
            int row = wm * 32 + mt * 16 + g;
            int col = wn * 96 + nt * 8 + 2 * tig;
            float* c = acc[mt][nt];
            *(float2*)&Cs[row * 196 + col]       = make_float2(c[0], c[1]);
            *(float2*)&Cs[(row + 8) * 196 + col] = make_float2(c[2], c[3]);
        }
    __syncthreads();

    // ---- Cs -> global (proven layouts) ----
    if (z == 1) {       // K: pair-interleaved cells, dims 0..9
        const int p = tid >> 2, tq = tid & 3;        // 64 row-pairs x 4 col-quads
        const int grow0 = row0 + 2 * p;
        const int b = grow0 >> 11;
        const int s2 = ((grow0 & 2047) >> 1);
        const float* r0 = &Cs[(2 * p) * 196];
        const float* r1 = &Cs[(2 * p + 1) * 196];
        #pragma unroll
        for (int hh = 0; hh < 4; hh++) {
            const int h = tq * 4 + hh;
            u64* cell = (u64*)(g_ki + ((size_t)(b * NH + h) * (NS / 2) + s2) * KCELL);
            #pragma unroll
            for (int j = 0; j < 10; j += 2) {
                ulonglong2 v;
                v.x = pack2(r0[h * 12 + j],     r1[h * 12 + j]);
                v.y = pack2(r0[h * 12 + j + 1], r1[h * 12 + j + 1]);
                *(ulonglong2*)(cell + j) = v;
            }
        }
    } else {            // Q / V: straight 12-stride rows
        const int row = tid >> 1, half = tid & 1;
        const int grow = row0 + row;
        const int b = grow >> 11, s = grow & 2047;
        const float* src = &Cs[row * 196];
        float* base = (z == 0) ? g_qp : g_vp;
        #pragma unroll
        for (int hh = 0; hh < 8; hh++) {
            const int h = half * 8 + hh;
            const float* fs = src + h * 12;
            float* dst = base + ((size_t)(b * NH + h) * NS + s) * DP;
            *(float4*)(dst + 0) = make_float4(fs[0], fs[1], fs[2], fs[3]);
            *(float4*)(dst + 4) = make_float4(fs[4], fs[5], fs[6], fs[7]);
            if (z == 0) *(float2*)(dst + 8) = make_float2(fs[8], fs[9]);
            else        *(float4*)(dst + 8) = make_float4(fs[8], fs[9], fs[10], fs[11]);
        }
    }
}

// ---------------------------------------------------------------------------
// Kernel 2: attention (verbatim from the 682.7us best). grid (2, 64),
// 512 threads; 2 q rows/thread; K pair-interleaved, V straight in smem.
// ---------------------------------------------------------------------------
__global__ __launch_bounds__(512, 1) void attn_kernel()
{
    extern __shared__ float smem[];
    float* ksf = smem;                     // [1024 cells][20]
    float* vs  = smem + 1024 * KCELL;      // [2048][12]
    const int bh = blockIdx.y;
    const int tid = threadIdx.x;

    {
        const float4* src = (const float4*)(g_ki + (size_t)bh * (NS / 2) * KCELL);
        float4* dst = (float4*)ksf;
        for (int i = tid; i < NS / 2 * KCELL / 4; i += 512) dst[i] = src[i];
        const float4* vsrc = (const float4*)(g_vp + (size_t)bh * NS * DP);
        float4* vdst = (float4*)vs;
        for (int i = tid; i < NS * DP / 4; i += 512) vdst[i] = vsrc[i];
    }
    __syncthreads();

    const int rowA = blockIdx.x * 1024 + tid;
    const int rowB = rowA + 512;

    u64 qA[10], qB[10];
    {
        const float* qr = g_qp + ((size_t)bh * NS + rowA) * DP;
        float4 a = *(const float4*)qr, bq = *(const float4*)(qr + 4);
        float2 c = *(const float2*)(qr + 8);
        float q[10] = { a.x, a.y, a.z, a.w, bq.x, bq.y, bq.z, bq.w, c.x, c.y };
        #pragma unroll
        for (int i = 0; i < 10; i++) qA[i] = pack2(q[i], q[i]);
    }
    {
        const float* qr = g_qp + ((size_t)bh * NS + rowB) * DP;
        float4 a = *(const float4*)qr, bq = *(const float4*)(qr + 4);
        float2 c = *(const float2*)(qr + 8);
        float q[10] = { a.x, a.y, a.z, a.w, bq.x, bq.y, bq.z, bq.w, c.x, c.y };
        #pragma unroll
        for (int i = 0; i < 10; i++) qB[i] = pack2(q[i], q[i]);
    }

    float lA = 0.0f, lB = 0.0f;
    u64 accA[6] = {0,0,0,0,0,0}, accB[6] = {0,0,0,0,0,0};
    const ulonglong2* ks2 = (const ulonglong2*)ksf;

    #pragma unroll 2
    for (int t2 = 0; t2 < NS / 2; t2++) {
        ulonglong2 k0 = ks2[(size_t)t2 * 5 + 0];
        ulonglong2 k1 = ks2[(size_t)t2 * 5 + 1];
        ulonglong2 k2 = ks2[(size_t)t2 * 5 + 2];
        ulonglong2 k3 = ks2[(size_t)t2 * 5 + 3];
        ulonglong2 k4 = ks2[(size_t)t2 * 5 + 4];

        u64 sA = 0ull, sB = 0ull;
        sA = ffma2(qA[0], k0.x, sA);  sB = ffma2(qB[0], k0.x, sB);
        sA = ffma2(qA[1], k0.y, sA);  sB = ffma2(qB[1], k0.y, sB);
        sA = ffma2(qA[2], k1.x, sA);  sB = ffma2(qB[2], k1.x, sB);
        sA = ffma2(qA[3], k1.y, sA);  sB = ffma2(qB[3], k1.y, sB);
        sA = ffma2(qA[4], k2.x, sA);  sB = ffma2(qB[4], k2.x, sB);
        sA = ffma2(qA[5], k2.y, sA);  sB = ffma2(qB[5], k2.y, sB);
        sA = ffma2(qA[6], k3.x, sA);  sB = ffma2(qB[6], k3.x, sB);
        sA = ffma2(qA[7], k3.y, sA);  sB = ffma2(qB[7], k3.y, sB);
        sA = ffma2(qA[8], k4.x, sA);  sB = ffma2(qB[8], k4.x, sB);
        sA = ffma2(qA[9], k4.y, sA);  sB = ffma2(qB[9], k4.y, sB);

        float s0A, s1A, s0B, s1B;
        unpack2(sA, s0A, s1A);
        unpack2(sB, s0B, s1B);
        float p0A = ex2f(s0A), p1A = ex2f(s1A);
        float p0B = ex2f(s0B), p1B = ex2f(s1B);
        lA += p0A + p1A;
        lB += p0B + p1B;
        u64 pp0A = pack2(p0A, p0A), pp1A = pack2(p1A, p1A);
        u64 pp0B = pack2(p0B, p0B), pp1B = pack2(p1B, p1B);

        const ulonglong2* vp2 = (const ulonglong2*)(vs + (size_t)(2 * t2) * DP);
        ulonglong2 va = vp2[0], vb = vp2[1], vc = vp2[2];
        ulonglong2 vd = vp2[3], ve = vp2[4], vf = vp2[5];

        accA[0] = ffma2(pp0A, va.x, accA[0]);  accB[0] = ffma2(pp0B, va.x, accB[0]);
        accA[1] = ffma2(pp0A, va.y, accA[1]);  accB[1] = ffma2(pp0B, va.y, accB[1]);
        accA[2] = ffma2(pp0A, vb.x, accA[2]);  accB[2] = ffma2(pp0B, vb.x, accB[2]);
        accA[3] = ffma2(pp0A, vb.y, accA[3]);  accB[3] = ffma2(pp0B, vb.y, accB[3]);
        accA[4] = ffma2(pp0A, vc.x, accA[4]);  accB[4] = ffma2(pp0B, vc.x, accB[4]);
        accA[5] = ffma2(pp0A, vc.y, accA[5]);  accB[5] = ffma2(pp0B, vc.y, accB[5]);
        accA[0] = ffma2(pp1A, vd.x, accA[0]);  accB[0] = ffma2(pp1B, vd.x, accB[0]);
        accA[1] = ffma2(pp1A, vd.y, accA[1]);  accB[1] = ffma2(pp1B, vd.y, accB[1]);
        accA[2] = ffma2(pp1A, ve.x, accA[2]);  accB[2] = ffma2(pp1B, ve.x, accB[2]);
        accA[3] = ffma2(pp1A, ve.y, accA[3]);  accB[3] = ffma2(pp1B, ve.y, accB[3]);
        accA[4] = ffma2(pp1A, vf.x, accA[4]);  accB[4] = ffma2(pp1B, vf.x, accB[4]);
        accA[5] = ffma2(pp1A, vf.y, accA[5]);  accB[5] = ffma2(pp1B, vf.y, accB[5]);
    }

    const int b = bh >> 4, h = bh & 15;
    {
        float inv = 1.0f / lA;
        float o[12];
        #pragma unroll
        for (int j = 0; j < 6; j++) unpack2(accA[j], o[2 * j], o[2 * j + 1]);
        float* dst = g_heads + (size_t)(b * NS + rowA) * NCOL + h * NDV;
        *(float4*)(dst + 0) = make_float4(o[0] * inv, o[1] * inv, o[2]  * inv, o[3]  * inv);
        *(float4*)(dst + 4) = make_float4(o[4] * inv, o[5] * inv, o[6]  * inv, o[7]  * inv);
        *(float4*)(dst + 8) = make_float4(o[8] * inv, o[9] * inv, o[10] * inv, o[11] * inv);
    }
    {
        float inv = 1.0f / lB;
        float o[12];
        #pragma unroll
        for (int j = 0; j < 6; j++) unpack2(accB[j], o[2 * j], o[2 * j + 1]);
        float* dst = g_heads + (size_t)(b * NS + rowB) * NCOL + h * NDV;
        *(float4*)(dst + 0) = make_float4(o[0] * inv, o[1] * inv, o[2]  * inv, o[3]  * inv);
        *(float4*)(dst + 4) = make_float4(o[4] * inv, o[5] * inv, o[6]  * inv, o[7]  * inv);
        *(float4*)(dst + 8) = make_float4(o[8] * inv, o[9] * inv, o[10] * inv, o[11] * inv);
    }
}

// ---------------------------------------------------------------------------
// Kernel 3: output projection (proven). [8192,192] x [192,1024].
// ---------------------------------------------------------------------------
__global__ __launch_bounds__(256, 2) void outproj_kernel(
    const float* __restrict__ WO, float* __restrict__ out)
{
    __shared__ u64 As2[16][64];
    __shared__ float Bs[16 * 128];
    const int tid = threadIdx.x;
    const int tyy = tid >> 5, txx = tid & 31;
    const int row0 = blockIdx.y * 64;
    const int col0 = blockIdx.x * 128;
    const int lr = tid >> 2, lseg = tid & 3;

    int woff[8], soff[8];
    #pragma unroll
    for (int i = 0; i < 8; i++) {
        int e = i * 256 + tid;
        int kk = e >> 7, c = e & 127;
        woff[i] = kk * ND + col0 + c;
        soff[i] = kk * 128 + c;
    }
    const float* aptr = g_heads + (size_t)(row0 + lr) * NCOL + lseg * 4;

    float4 areg = *(const float4*)aptr;
    float breg[8];
    #pragma unroll
    for (int i = 0; i < 8; i++) breg[i] = WO[woff[i]];

    u64 acc[8][2];
    #pragma unroll
    for (int r = 0; r < 8; r++) { acc[r][0] = 0ull; acc[r][1] = 0ull; }

    const int NT = NCOL / 16;
    for (int t = 0; t < NT; t++) {
        As2[lseg * 4 + 0][lr] = pack2(areg.x, areg.x);
        As2[lseg * 4 + 1][lr] = pack2(areg.y, areg.y);
        As2[lseg * 4 + 2][lr] = pack2(areg.z, areg.z);
        As2[lseg * 4 + 3][lr] = pack2(areg.w, areg.w);
        #pragma unroll
        for (int i = 0; i < 8; i++) Bs[soff[i]] = breg[i];
        __syncthreads();

        if (t < NT - 1) {
            areg = *(const float4*)(aptr + (t + 1) * 16);
            int kadd = (t + 1) * 16 * ND;
            #pragma unroll
            for (int i = 0; i < 8; i++) breg[i] = WO[woff[i] + kadd];
        }

        #pragma unroll
        for (int kk = 0; kk < 16; kk++) {
            ulonglong2 bv = *(const ulonglong2*)&Bs[kk * 128 + txx * 4];
            #pragma unroll
            for (int r = 0; r < 8; r++) {
                u64 a = As2[kk][tyy * 8 + r];
                acc[r][0] = ffma2(a, bv.x, acc[r][0]);
                acc[r][1] = ffma2(a, bv.y, acc[r][1]);
            }
        }
        __syncthreads();
    }

    #pragma unroll
    for (int r = 0; r < 8; r++) {
        float o[4];
        unpack2(acc[r][0], o[0], o[1]);
        unpack2(acc[r][1], o[2], o[3]);
        float* dst = out + (size_t)(row0 + tyy * 8 + r) * ND + col0 + txx * 4;
        *(float4*)dst = make_float4(o[0], o[1], o[2], o[3]);
    }
}

// ---------------------------------------------------------------------------
extern "C" void kernel_launch(void* const* d_in, const int* in_sizes, int n_in,
                              void* d_out, int out_size)
{
    const float* Q  = (const float*)d_in[0];
    const float* K  = (const float*)d_in[1];
    const float* V  = (const float*)d_in[2];
    const float* WQ = (const float*)d_in[3];
    const float* WK = (const float*)d_in[4];
    const float* WV = (const float*)d_in[5];
    const float* WO = (const float*)d_in[6];
    float* out = (float*)d_out;

    const int attn_smem = (1024 * KCELL + NS * DP) * 4;   // 80KB + 96KB
    cudaFuncSetAttribute(attn_kernel, cudaFuncAttributeMaxDynamicSharedMemorySize, attn_smem);
    cudaFuncSetAttribute(proj_mma_kernel, cudaFuncAttributeMaxDynamicSharedMemorySize, PROJ_SMEM);

    prep_kernel<<<3 * ND * NCOL / 256, 256>>>(WQ, WK, WV);

    dim3 g1(NROW / 128, 1, 3);
    proj_mma_kernel<<<g1, 256, PROJ_SMEM>>>(Q, K, V);

    dim3 g2(NS / 1024, NB * NH);
    attn_kernel<<<g2, 512, attn_smem>>>();

    dim3 g3(ND / 128, NROW / 64);
    outproj_kernel<<<g3, 256>>>(WO, out);
}

// round 15
// speedup vs baseline: 1.5638x; 1.3874x over previous
#include <cuda_runtime.h>
#include <math.h>
#include <stdint.h>

#define NB 4
#define NS 2048
#define ND 1024
#define NH 16
#define NDK 10
#define NDV 12
#define DP 12
#define NROW (NB*NS)          // 8192
#define NCOL (NH*DP)          // 192
#define KCELL 20              // 2 keys x 10 dims, pair-interleaved
#define NFQ 98304             // per-z QKV B-plane u32 count = 64kt*24nt*64
#define NFO 98304             // WO plane u32 count = 12kt*128nt*64

// scratch (device globals: no allocation allowed)
__device__ unsigned int g_bh[3*NFQ];         // QKV weights bf16-hi frag planes (Q scale folded)
__device__ unsigned int g_bl[3*NFQ];         // lo planes
__device__ unsigned int g_woh[NFO];          // WO bf16-hi frag plane
__device__ unsigned int g_wol[NFO];          // WO lo plane
__device__ float g_qp[NB*NH*NS*DP];          // q*(log2e/sqrt10), 12-stride, cols 0..9 valid
__device__ float g_ki[NB*NH*(NS/2)*KCELL];   // K pairs: cell[j] = (k_{2t}[j], k_{2t+1}[j])
__device__ float g_vp[NB*NH*NS*DP];          // v, straight 12-stride rows
__device__ float g_heads[NROW*NCOL];         // concat heads [b*S+s][h*12+j]

typedef unsigned long long u64;
typedef unsigned int u32;

__device__ __forceinline__ u64 ffma2(u64 a, u64 b, u64 c) {
    u64 d; asm("fma.rn.f32x2 %0, %1, %2, %3;" : "=l"(d) : "l"(a), "l"(b), "l"(c)); return d;
}
__device__ __forceinline__ u64 pack2(float x, float y) {
    u64 r; asm("mov.b64 %0, {%1, %2};" : "=l"(r) : "f"(x), "f"(y)); return r;
}
__device__ __forceinline__ void unpack2(u64 v, float& x, float& y) {
    asm("mov.b64 {%0, %1}, %2;" : "=f"(x), "=f"(y) : "l"(v));
}
__device__ __forceinline__ float ex2f(float x) {
    float y; asm("ex2.approx.f32 %0, %1;" : "=f"(y) : "f"(x)); return y;
}
// cvt.rn.bf16x2.f32 d, a, b -> upper16 = bf16(a), lower16 = bf16(b)
__device__ __forceinline__ u32 cvt_bf16x2(float hi, float lo) {
    u32 r; asm("cvt.rn.bf16x2.f32 %0, %1, %2;" : "=r"(r) : "f"(hi), "f"(lo)); return r;
}
// split fp32 pair (x0 -> low half, x1 -> high half) into bf16 hi/lo packed u32s
__device__ __forceinline__ void split2(float x0, float x1, u32& hi, u32& lo) {
    hi = cvt_bf16x2(x1, x0);
    float h0 = __uint_as_float(hi << 16);
    float h1 = __uint_as_float(hi & 0xFFFF0000u);
    lo = cvt_bf16x2(x1 - h1, x0 - h0);
}
__device__ __forceinline__ void mma_bf16(float* c, const u32* a, u32 b0, u32 b1) {
    asm volatile(
        "mma.sync.aligned.m16n8k16.row.col.f32.bf16.bf16.f32 "
        "{%0,%1,%2,%3}, {%4,%5,%6,%7}, {%8,%9}, {%0,%1,%2,%3};"
        : "+f"(c[0]), "+f"(c[1]), "+f"(c[2]), "+f"(c[3])
        : "r"(a[0]), "r"(a[1]), "r"(a[2]), "r"(a[3]), "r"(b0), "r"(b1));
}

// ---------------------------------------------------------------------------
// Kernel 0a: QKV weights -> bf16 hi/lo m16n8k16 B-fragment planes.
// One thread per (z, k-pair, n). u32 packs (k even -> low16, k odd -> high16).
// addr = z*NFQ + kt*1536 + nt*64 + r*32 + nr*4 + p  (r=(k2>>2)&1, p=k2&3)
// ---------------------------------------------------------------------------
__global__ __launch_bounds__(256) void prep_qkv_kernel(
    const float* __restrict__ WQ, const float* __restrict__ WK, const float* __restrict__ WV)
{
    int idx = blockIdx.x * 256 + threadIdx.x;     // < 3*512*192
    int z = idx / (512 * NCOL);
    int rem = idx - z * 512 * NCOL;
    int k2 = rem / NCOL, n = rem - k2 * NCOL;
    int h = n / DP, j = n - h * DP;
    const float* W = (z == 0) ? WQ : ((z == 1) ? WK : WV);
    int dout = (z == 2) ? NDV : NDK;
    float w0 = 0.0f, w1 = 0.0f;
    if (j < dout) {
        w0 = W[(h * ND + 2 * k2) * dout + j];
        w1 = W[(h * ND + 2 * k2 + 1) * dout + j];
    }
    if (z == 0) {
        const float sc = 1.4426950408889634f * rsqrtf(10.0f);
        w0 *= sc; w1 *= sc;
    }
    u32 hi, lo;
    split2(w0, w1, hi, lo);
    int kt = k2 >> 3, r = (k2 >> 2) & 1, p = k2 & 3;
    int nt = n >> 3, nr = n & 7;
    int addr = z * NFQ + kt * 1536 + nt * 64 + r * 32 + nr * 4 + p;
    g_bh[addr] = hi;
    g_bl[addr] = lo;
}

// ---------------------------------------------------------------------------
// Kernel 0b: WO -> bf16 hi/lo fragment planes. WO is [192, 1024].
// ---------------------------------------------------------------------------
__global__ __launch_bounds__(256) void prep_wo_kernel(const float* __restrict__ WO)
{
    int idx = blockIdx.x * 256 + threadIdx.x;     // < 96*1024
    int k2 = idx / ND, n = idx - k2 * ND;
    float w0 = WO[(2 * k2) * ND + n];
    float w1 = WO[(2 * k2 + 1) * ND + n];
    u32 hi, lo;
    split2(w0, w1, hi, lo);
    int kt = k2 >> 3, r = (k2 >> 2) & 1, p = k2 & 3;
    int nt = n >> 3, nr = n & 7;
    int addr = kt * 8192 + nt * 64 + r * 32 + nr * 4 + p;
    g_woh[addr] = hi;
    g_wol[addr] = lo;
}

// ---------------------------------------------------------------------------
// Kernel 1: QKV projection via bf16 m16n8k16 mma.sync, 3-way split.
// grid (64,1,3), 256 threads = 8 warps (2m x 4n); CTA 128x192, warp 64x48.
// A split once per 32-k chunk into smem bf16 planes [128][20] u32 (pad-20:
// conflict-free for the (g,tig) fragment pattern). Epilogue via Cs smem.
// ---------------------------------------------------------------------------
#define PROJ_SMEM (128*196*4)   // 100352 B; A planes (20480 B) alias low part

__global__ __launch_bounds__(256) void proj_mma_kernel(
    const float* __restrict__ Q, const float* __restrict__ K, const float* __restrict__ V)
{
    extern __shared__ char smraw[];
    u32* AH = (u32*)smraw;              // [128][20]
    u32* AL = AH + 128 * 20;            // [128][20]
    float* Cs = (float*)smraw;          // [128][196] during epilogue

    const int z = blockIdx.z;
    const float* X = (z == 0) ? Q : ((z == 1) ? K : V);
    const u32* Bhi = g_bh + (size_t)z * NFQ;
    const u32* Blo = g_bl + (size_t)z * NFQ;

    const int tid = threadIdx.x;
    const int warp = tid >> 5, lane = tid & 31;
    const int wm = warp & 1, wn = warp >> 1;      // 2m x 4n
    const int g = lane >> 2, tig = lane & 3;
    const int row0 = blockIdx.x * 128;

    float acc[4][6][4];
    #pragma unroll
    for (int mt = 0; mt < 4; mt++)
        #pragma unroll
        for (int nt = 0; nt < 6; nt++)
            #pragma unroll
            for (int c = 0; c < 4; c++) acc[mt][nt][c] = 0.0f;

    for (int t = 0; t < ND / 32; t++) {
        // stage + split A chunk [128][32] -> bf16 hi/lo planes
        #pragma unroll
        for (int i = 0; i < 4; i++) {
            int f = tid + i * 256;
            int row = f >> 3, seg = f & 7;
            float4 v = *(const float4*)(X + (size_t)(row0 + row) * ND + t * 32 + seg * 4);
            u32 h01, l01, h23, l23;
            split2(v.x, v.y, h01, l01);
            split2(v.z, v.w, h23, l23);
            *(uint2*)&AH[row * 20 + seg * 2] = make_uint2(h01, h23);
            *(uint2*)&AL[row * 20 + seg * 2] = make_uint2(l01, l23);
        }
        __syncthreads();

        #pragma unroll
        for (int ks = 0; ks < 2; ks++) {
            const int kt = t * 2 + ks;
            u32 ah[4][4], al[4][4];
            #pragma unroll
            for (int mt = 0; mt < 4; mt++) {
                int r0w = (wm * 64 + mt * 16 + g) * 20 + ks * 8 + tig;
                int r1w = r0w + 8 * 20;
                ah[mt][0] = AH[r0w];     ah[mt][1] = AH[r1w];
                ah[mt][2] = AH[r0w + 4]; ah[mt][3] = AH[r1w + 4];
                al[mt][0] = AL[r0w];     al[mt][1] = AL[r1w];
                al[mt][2] = AL[r0w + 4]; al[mt][3] = AL[r1w + 4];
            }
            const u32* bh = Bhi + kt * 1536 + (wn * 6) * 64 + lane;
            const u32* bl = Blo + kt * 1536 + (wn * 6) * 64 + lane;
            #pragma unroll
            for (int nt = 0; nt < 6; nt++) {
                u32 b0h = bh[nt * 64], b1h = bh[nt * 64 + 32];
                u32 b0l = bl[nt * 64], b1l = bl[nt * 64 + 32];
                #pragma unroll
                for (int mt = 0; mt < 4; mt++) {
                    mma_bf16(acc[mt][nt], ah[mt], b0h, b1h);
                    mma_bf16(acc[mt][nt], ah[mt], b0l, b1l);
                    mma_bf16(acc[mt][nt], al[mt], b0h, b1h);
                }
            }
        }
        __syncthreads();
    }

    // ---- epilogue: fragments -> Cs ----
    #pragma unroll
    for (int mt = 0; mt < 4; mt++)
        #pragma unroll
        for (int nt = 0; nt < 6; nt++) {
            int row = wm * 64 + mt * 16 + g;
            int col = wn * 48 + nt * 8 + 2 * tig;
            float* c = acc[mt][nt];
            *(float2*)&Cs[row * 196 + col]       = make_float2(c[0], c[1]);
            *(float2*)&Cs[(row + 8) * 196 + col] = make_float2(c[2], c[3]);
        }
    __syncthreads();

    // ---- Cs -> global (proven layouts) ----
    if (z == 1) {       // K: pair-interleaved cells, dims 0..9
        const int p = tid >> 2, tq = tid & 3;
        const int grow0 = row0 + 2 * p;
        const int b = grow0 >> 11;
        const int s2 = ((grow0 & 2047) >> 1);
        const float* r0 = &Cs[(2 * p) * 196];
        const float* r1 = &Cs[(2 * p + 1) * 196];
        #pragma unroll
        for (int hh = 0; hh < 4; hh++) {
            const int h = tq * 4 + hh;
            u64* cell = (u64*)(g_ki + ((size_t)(b * NH + h) * (NS / 2) + s2) * KCELL);
            #pragma unroll
            for (int j = 0; j < 10; j += 2) {
                ulonglong2 v;
                v.x = pack2(r0[h * 12 + j],     r1[h * 12 + j]);
                v.y = pack2(r0[h * 12 + j + 1], r1[h * 12 + j + 1]);
                *(ulonglong2*)(cell + j) = v;
            }
        }
    } else {            // Q / V: straight 12-stride rows
        const int row = tid >> 1, half = tid & 1;
        const int grow = row0 + row;
        const int b = grow >> 11, s = grow & 2047;
        const float* src = &Cs[row * 196];
        float* base = (z == 0) ? g_qp : g_vp;
        #pragma unroll
        for (int hh = 0; hh < 8; hh++) {
            const int h = half * 8 + hh;
            const float* fs = src + h * 12;
            float* dst = base + ((size_t)(b * NH + h) * NS + s) * DP;
            *(float4*)(dst + 0) = make_float4(fs[0], fs[1], fs[2], fs[3]);
            *(float4*)(dst + 4) = make_float4(fs[4], fs[5], fs[6], fs[7]);
            if (z == 0) *(float2*)(dst + 8) = make_float2(fs[8], fs[9]);
            else        *(float4*)(dst + 8) = make_float4(fs[8], fs[9], fs[10], fs[11]);
        }
    }
}

// ---------------------------------------------------------------------------
// Kernel 2: attention (verbatim from best). grid (2, 64), 512 threads;
// 2 q rows/thread; K pair-interleaved, V straight in smem.
// ---------------------------------------------------------------------------
__global__ __launch_bounds__(512, 1) void attn_kernel()
{
    extern __shared__ float smem[];
    float* ksf = smem;                     // [1024 cells][20]
    float* vs  = smem + 1024 * KCELL;      // [2048][12]
    const int bh = blockIdx.y;
    const int tid = threadIdx.x;

    {
        const float4* src = (const float4*)(g_ki + (size_t)bh * (NS / 2) * KCELL);
        float4* dst = (float4*)ksf;
        for (int i = tid; i < NS / 2 * KCELL / 4; i += 512) dst[i] = src[i];
        const float4* vsrc = (const float4*)(g_vp + (size_t)bh * NS * DP);
        float4* vdst = (float4*)vs;
        for (int i = tid; i < NS * DP / 4; i += 512) vdst[i] = vsrc[i];
    }
    __syncthreads();

    const int rowA = blockIdx.x * 1024 + tid;
    const int rowB = rowA + 512;

    u64 qA[10], qB[10];
    {
        const float* qr = g_qp + ((size_t)bh * NS + rowA) * DP;
        float4 a = *(const float4*)qr, bq = *(const float4*)(qr + 4);
        float2 c = *(const float2*)(qr + 8);
        float q[10] = { a.x, a.y, a.z, a.w, bq.x, bq.y, bq.z, bq.w, c.x, c.y };
        #pragma unroll
        for (int i = 0; i < 10; i++) qA[i] = pack2(q[i], q[i]);
    }
    {
        const float* qr = g_qp + ((size_t)bh * NS + rowB) * DP;
        float4 a = *(const float4*)qr, bq = *(const float4*)(qr + 4);
        float2 c = *(const float2*)(qr + 8);
        float q[10] = { a.x, a.y, a.z, a.w, bq.x, bq.y, bq.z, bq.w, c.x, c.y };
        #pragma unroll
        for (int i = 0; i < 10; i++) qB[i] = pack2(q[i], q[i]);
    }

    float lA = 0.0f, lB = 0.0f;
    u64 accA[6] = {0,0,0,0,0,0}, accB[6] = {0,0,0,0,0,0};
    const ulonglong2* ks2 = (const ulonglong2*)ksf;

    #pragma unroll 2
    for (int t2 = 0; t2 < NS / 2; t2++) {
        ulonglong2 k0 = ks2[(size_t)t2 * 5 + 0];
        ulonglong2 k1 = ks2[(size_t)t2 * 5 + 1];
        ulonglong2 k2 = ks2[(size_t)t2 * 5 + 2];
        ulonglong2 k3 = ks2[(size_t)t2 * 5 + 3];
        ulonglong2 k4 = ks2[(size_t)t2 * 5 + 4];

        u64 sA = 0ull, sB = 0ull;
        sA = ffma2(qA[0], k0.x, sA);  sB = ffma2(qB[0], k0.x, sB);
        sA = ffma2(qA[1], k0.y, sA);  sB = ffma2(qB[1], k0.y, sB);
        sA = ffma2(qA[2], k1.x, sA);  sB = ffma2(qB[2], k1.x, sB);
        sA = ffma2(qA[3], k1.y, sA);  sB = ffma2(qB[3], k1.y, sB);
        sA = ffma2(qA[4], k2.x, sA);  sB = ffma2(qB[4], k2.x, sB);
        sA = ffma2(qA[5], k2.y, sA);  sB = ffma2(qB[5], k2.y, sB);
        sA = ffma2(qA[6], k3.x, sA);  sB = ffma2(qB[6], k3.x, sB);
        sA = ffma2(qA[7], k3.y, sA);  sB = ffma2(qB[7], k3.y, sB);
        sA = ffma2(qA[8], k4.x, sA);  sB = ffma2(qB[8], k4.x, sB);
        sA = ffma2(qA[9], k4.y, sA);  sB = ffma2(qB[9], k4.y, sB);

        float s0A, s1A, s0B, s1B;
        unpack2(sA, s0A, s1A);
        unpack2(sB, s0B, s1B);
        float p0A = ex2f(s0A), p1A = ex2f(s1A);
        float p0B = ex2f(s0B), p1B = ex2f(s1B);
        lA += p0A + p1A;
        lB += p0B + p1B;
        u64 pp0A = pack2(p0A, p0A), pp1A = pack2(p1A, p1A);
        u64 pp0B = pack2(p0B, p0B), pp1B = pack2(p1B, p1B);

        const ulonglong2* vp2 = (const ulonglong2*)(vs + (size_t)(2 * t2) * DP);
        ulonglong2 va = vp2[0], vb = vp2[1], vc = vp2[2];
        ulonglong2 vd = vp2[3], ve = vp2[4], vf = vp2[5];

        accA[0] = ffma2(pp0A, va.x, accA[0]);  accB[0] = ffma2(pp0B, va.x, accB[0]);
        accA[1] = ffma2(pp0A, va.y, accA[1]);  accB[1] = ffma2(pp0B, va.y, accB[1]);
        accA[2] = ffma2(pp0A, vb.x, accA[2]);  accB[2] = ffma2(pp0B, vb.x, accB[2]);
        accA[3] = ffma2(pp0A, vb.y, accA[3]);  accB[3] = ffma2(pp0B, vb.y, accB[3]);
        accA[4] = ffma2(pp0A, vc.x, accA[4]);  accB[4] = ffma2(pp0B, vc.x, accB[4]);
        accA[5] = ffma2(pp0A, vc.y, accA[5]);  accB[5] = ffma2(pp0B, vc.y, accB[5]);
        accA[0] = ffma2(pp1A, vd.x, accA[0]);  accB[0] = ffma2(pp1B, vd.x, accB[0]);
        accA[1] = ffma2(pp1A, vd.y, accA[1]);  accB[1] = ffma2(pp1B, vd.y, accB[1]);
        accA[2] = ffma2(pp1A, ve.x, accA[2]);  accB[2] = ffma2(pp1B, ve.x, accB[2]);
        accA[3] = ffma2(pp1A, ve.y, accA[3]);  accB[3] = ffma2(pp1B, ve.y, accB[3]);
        accA[4] = ffma2(pp1A, vf.x, accA[4]);  accB[4] = ffma2(pp1B, vf.x, accB[4]);
        accA[5] = ffma2(pp1A, vf.y, accA[5]);  accB[5] = ffma2(pp1B, vf.y, accB[5]);
    }

    const int b = bh >> 4, h = bh & 15;
    {
        float inv = 1.0f / lA;
        float o[12];
        #pragma unroll
        for (int j = 0; j < 6; j++) unpack2(accA[j], o[2 * j], o[2 * j + 1]);
        float* dst = g_heads + (size_t)(b * NS + rowA) * NCOL + h * NDV;
        *(float4*)(dst + 0) = make_float4(o[0] * inv, o[1] * inv, o[2]  * inv, o[3]  * inv);
        *(float4*)(dst + 4) = make_float4(o[4] * inv, o[5] * inv, o[6]  * inv, o[7]  * inv);
        *(float4*)(dst + 8) = make_float4(o[8] * inv, o[9] * inv, o[10] * inv, o[11] * inv);
    }
    {
        float inv = 1.0f / lB;
        float o[12];
        #pragma unroll
        for (int j = 0; j < 6; j++) unpack2(accB[j], o[2 * j], o[2 * j + 1]);
        float* dst = g_heads + (size_t)(b * NS + rowB) * NCOL + h * NDV;
        *(float4*)(dst + 0) = make_float4(o[0] * inv, o[1] * inv, o[2]  * inv, o[3]  * inv);
        *(float4*)(dst + 4) = make_float4(o[4] * inv, o[5] * inv, o[6]  * inv, o[7]  * inv);
        *(float4*)(dst + 8) = make_float4(o[8] * inv, o[9] * inv, o[10] * inv, o[11] * inv);
    }
}

// ---------------------------------------------------------------------------
// Kernel 3: output projection via bf16 m16n8k16 mma.sync, 3-way split.
// grid (8, 64): CTA 128 rows x 128 cols, K=192 in 6 chunks of 32.
// 256 threads = 8 warps (2m x 4n); warp 64x32 = 4mt x 4nt. Direct STG epilogue.
// ---------------------------------------------------------------------------
#define OUT_SMEM (128*20*4*2)    // 20480 B (bf16 hi/lo A planes)

__global__ __launch_bounds__(256) void outproj_mma_kernel(float* __restrict__ out)
{
    extern __shared__ char smraw[];
    u32* AH = (u32*)smraw;
    u32* AL = AH + 128 * 20;

    const int tid = threadIdx.x;
    const int warp = tid >> 5, lane = tid & 31;
    const int wm = warp & 1, wn = warp >> 1;
    const int g = lane >> 2, tig = lane & 3;
    const int row0 = blockIdx.y * 128;
    const int col0 = blockIdx.x * 128;

    float acc[4][4][4];
    #pragma unroll
    for (int mt = 0; mt < 4; mt++)
        #pragma unroll
        for (int nt = 0; nt < 4; nt++)
            #pragma unroll
            for (int c = 0; c < 4; c++) acc[mt][nt][c] = 0.0f;

    for (int t = 0; t < NCOL / 32; t++) {
        #pragma unroll
        for (int i = 0; i < 4; i++) {
            int f = tid + i * 256;
            int row = f >> 3, seg = f & 7;
            float4 v = *(const float4*)(g_heads + (size_t)(row0 + row) * NCOL + t * 32 + seg * 4);
            u32 h01, l01, h23, l23;
            split2(v.x, v.y, h01, l01);
            split2(v.z, v.w, h23, l23);
            *(uint2*)&AH[row * 20 + seg * 2] = make_uint2(h01, h23);
            *(uint2*)&AL[row * 20 + seg * 2] = make_uint2(l01, l23);
        }
        __syncthreads();

        #pragma unroll
        for (int ks = 0; ks < 2; ks++) {
            const int kt = t * 2 + ks;
            u32 ah[4][4], al[4][4];
            #pragma unroll
            for (int mt = 0; mt < 4; mt++) {
                int r0w = (wm * 64 + mt * 16 + g) * 20 + ks * 8 + tig;
                int r1w = r0w + 8 * 20;
                ah[mt][0] = AH[r0w];     ah[mt][1] = AH[r1w];
                ah[mt][2] = AH[r0w + 4]; ah[mt][3] = AH[r1w + 4];
                al[mt][0] = AL[r0w];     al[mt][1] = AL[r1w];
                al[mt][2] = AL[r0w + 4]; al[mt][3] = AL[r1w + 4];
            }
            const int gnt0 = (col0 >> 3) + wn * 4;
            const u32* bh = g_woh + kt * 8192 + gnt0 * 64 + lane;
            const u32* bl = g_wol + kt * 8192 + gnt0 * 64 + lane;
            #pragma unroll
            for (int nt = 0; nt < 4; nt++) {
                u32 b0h = bh[nt * 64], b1h = bh[nt * 64 + 32];
                u32 b0l = bl[nt * 64], b1l = bl[nt * 64 + 32];
                #pragma unroll
                for (int mt = 0; mt < 4; mt++) {
                    mma_bf16(acc[mt][nt], ah[mt], b0h, b1h);
                    mma_bf16(acc[mt][nt], ah[mt], b0l, b1l);
                    mma_bf16(acc[mt][nt], al[mt], b0h, b1h);
                }
            }
        }
        __syncthreads();
    }

    // direct epilogue
    #pragma unroll
    for (int mt = 0; mt < 4; mt++)
        #pragma unroll
        for (int nt = 0; nt < 4; nt++) {
            int row = row0 + wm * 64 + mt * 16 + g;
            int col = col0 + wn * 32 + nt * 8 + 2 * tig;
            float* c = acc[mt][nt];
            *(float2*)&out[(size_t)row * ND + col]       = make_float2(c[0], c[1]);
            *(float2*)&out[(size_t)(row + 8) * ND + col] = make_float2(c[2], c[3]);
        }
}

// ---------------------------------------------------------------------------
extern "C" void kernel_launch(void* const* d_in, const int* in_sizes, int n_in,
                              void* d_out, int out_size)
{
    const float* Q  = (const float*)d_in[0];
    const float* K  = (const float*)d_in[1];
    const float* V  = (const float*)d_in[2];
    const float* WQ = (const float*)d_in[3];
    const float* WK = (const float*)d_in[4];
    const float* WV = (const float*)d_in[5];
    const float* WO = (const float*)d_in[6];
    float* out = (float*)d_out;

    const int attn_smem = (1024 * KCELL + NS * DP) * 4;   // 80KB + 96KB
    cudaFuncSetAttribute(attn_kernel, cudaFuncAttributeMaxDynamicSharedMemorySize, attn_smem);
    cudaFuncSetAttribute(proj_mma_kernel, cudaFuncAttributeMaxDynamicSharedMemorySize, PROJ_SMEM);
    cudaFuncSetAttribute(outproj_mma_kernel, cudaFuncAttributeMaxDynamicSharedMemorySize, OUT_SMEM);

    prep_qkv_kernel<<<3 * 512 * NCOL / 256, 256>>>(WQ, WK, WV);
    prep_wo_kernel<<<96 * ND / 256, 256>>>(WO);

    dim3 g1(NROW / 128, 1, 3);
    proj_mma_kernel<<<g1, 256, PROJ_SMEM>>>(Q, K, V);

    dim3 g2(NS / 1024, NB * NH);
    attn_kernel<<<g2, 512, attn_smem>>>();

    dim3 g3(ND / 128, NROW / 128);
    outproj_mma_kernel<<<g3, 256, OUT_SMEM>>>(out);
}